// round 10
// baseline (speedup 1.0000x reference)
#include <cuda_runtime.h>
#include <cuda_bf16.h>
#include <cstdint>

// ============================================================================
// ResidualBlockWithPointsBase — mma.sync BF16 3-pass + LDG/STS gather
//   y1 = conv(x, W1); BN1 fold; y2 = conv(relu(bn1(y1)) [folded], W2);
//   BN2 fold; out = relu(bn2(y2) + x)
// conv: persistent CTAs over (k, 128-edge tile):
//   gather via plain LDG.128 -> STS.128 (single smem buffer, conflict-free
//   half-offset layout), optional BN+ReLU fold, in-register bf16 hi/lo split,
//   warp mma.m16n8k16 (3-term), W pre-split bf16x2 smem (pad-36),
//   red.global.add.v4.f32 scatter (column-permuted). 2 CTAs/SM.
// ============================================================================

#define MAXN 100352

__device__ float g_y1[MAXN * 64];
__device__ float g_y2[MAXN * 64];
__device__ float2 g_stats[4 * 32];
__device__ float g_bn[4 * 64];

__device__ __forceinline__ void mma_bf16(float* d, const uint32_t* a, const uint32_t* b) {
    asm volatile(
        "mma.sync.aligned.m16n8k16.row.col.f32.bf16.bf16.f32 "
        "{%0,%1,%2,%3}, {%4,%5,%6,%7}, {%8,%9}, {%0,%1,%2,%3};"
        : "+f"(d[0]), "+f"(d[1]), "+f"(d[2]), "+f"(d[3])
        : "r"(a[0]), "r"(a[1]), "r"(a[2]), "r"(a[3]), "r"(b[0]), "r"(b[1]));
}
__device__ __forceinline__ void red_add_v4(float* g, float a, float b, float c, float d) {
    asm volatile("red.global.add.v4.f32 [%0], {%1, %2, %3, %4};"
                 :: "l"(g), "f"(a), "f"(b), "f"(c), "f"(d) : "memory");
}
// split float2 (f.x = even k, f.y = odd k) into bf16x2 hi and lo
__device__ __forceinline__ void split_bf16(float2 f, uint32_t& h, uint32_t& l) {
    __nv_bfloat162 hb = __floats2bfloat162_rn(f.x, f.y);
    float hx = __bfloat162float(__low2bfloat16(hb));
    float hy = __bfloat162float(__high2bfloat16(hb));
    __nv_bfloat162 lb = __floats2bfloat162_rn(f.x - hx, f.y - hy);
    h = *reinterpret_cast<uint32_t*>(&hb);
    l = *reinterpret_cast<uint32_t*>(&lb);
}

// smem layout (floats):
//   A: 128 rows x stride 72; half0 (k 0..31) at +0, half1 (k 32..63) at +36
//   W: bf16x2 hi/lo, [col][kpair] pad-36 (uint32)
#define A_STRIDE 72
#define OFF_W (128 * A_STRIDE)                // 9216
#define W_PAD 36
#define SMEM_FLOATS (OFF_W + 2 * 64 * W_PAD)  // 13824
#define SMEM_BYTES (SMEM_FLOATS * 4)          // 55296

// ---------------------------------------------------------------------------
template <bool BN>
__global__ __launch_bounds__(256, 2) void conv_mma_kernel(
    const float* __restrict__ xin,  // [N][64]
    const float* __restrict__ W,    // [K][64][64]
    const int* __restrict__ in_idx, const int* __restrict__ out_idx,
    float* __restrict__ yout,       // [N][64] pre-zeroed
    const float* __restrict__ bnp,  // scale[64], shift[64] (BN only)
    int nE, int K, int nblk) {
    extern __shared__ float sm[];
    float* Abuf = sm;
    uint32_t* Wh2 = (uint32_t*)(sm + OFF_W);
    uint32_t* Wl2 = Wh2 + 64 * W_PAD;

    const int tid = threadIdx.x;
    const int lane = tid & 31;
    const int wid = tid >> 5;
    const int gi = lane >> 2;
    const int tq = lane & 3;
    const int EB = (wid >> 1) * 32;    // warp's edge base
    const int NBASE = (wid & 1) * 32;  // warp's cout base

    const int grow = tid >> 1;         // gather row 0..127
    const int ghalf = tid & 1;         // k-half 0/1

    const int tilesPerK = (nE + 127) >> 7;
    const int total = K * tilesPerK;
    const int chunk = (total + nblk - 1) / nblk;
    const int it0 = blockIdx.x * chunk;
    const int it1 = min(it0 + chunk, total);
    if (it0 >= it1) return;

    auto load_idx = [&](int item) -> int {
        int k = item / tilesPerK;
        int e = (item - k * tilesPerK) * 128 + grow;
        return (e < nE) ? __ldg(in_idx + (size_t)k * nE + e) : 0;
    };

    int cur_k = -1;
    int cidx = load_idx(it0);

    for (int item = it0; item < it1; item++) {
        const int k = item / tilesPerK;
        const int tile = item - k * tilesPerK;
        const int ebase = tile * 128;

        if (k != cur_k) {  // W restage: bf16 hi/lo, k-pairs packed, col-permuted
            cur_k = k;
            const float* Wk = W + (size_t)k * 4096;
            for (int i = tid; i < 2048; i += 256) {
                int colP = i >> 5, j = i & 31;  // j = k-pair (k = 2j, 2j+1)
                int l16 = colP & 15;
                // inverse column permutation (for v4 scatter)
                int Lcol = (colP & ~15) + 4 * ((l16 >> 1) & 3) + 2 * ((l16 >> 3) & 1) + (l16 & 1);
                float w0 = __ldg(Wk + (size_t)(2 * j) * 64 + Lcol);
                float w1 = __ldg(Wk + (size_t)(2 * j + 1) * 64 + Lcol);
                uint32_t h, l;
                split_bf16(make_float2(w0, w1), h, l);
                Wh2[colP * W_PAD + j] = h;
                Wl2[colP * W_PAD + j] = l;
            }
        }

        // ---- gather: LDG.128 -> (BN fold) -> STS.128 ----
        {
            const float4* src = (const float4*)(xin + (size_t)cidx * 64 + ghalf * 32);
            float* dst = Abuf + grow * A_STRIDE + ghalf * 36;
#pragma unroll
            for (int j = 0; j < 8; j++) {
                float4 v = __ldg(src + j);
                if (BN) {
                    float4 s4 = __ldg((const float4*)bnp + ghalf * 8 + j);
                    float4 h4 = __ldg((const float4*)bnp + 16 + ghalf * 8 + j);
                    v.x = fmaxf(fmaf(v.x, s4.x, h4.x), 0.f);
                    v.y = fmaxf(fmaf(v.y, s4.y, h4.y), 0.f);
                    v.z = fmaxf(fmaf(v.z, s4.z, h4.z), 0.f);
                    v.w = fmaxf(fmaf(v.w, s4.w, h4.w), 0.f);
                }
                *(float4*)(dst + 4 * j) = v;
            }
        }
        cidx = (item + 1 < it1) ? load_idx(item + 1) : 0;  // prefetch next idx
        __syncthreads();

        // ---- compute: 2 m-tiles x 4 n-tiles, 4 k-chunks (k=16), 3 terms ----
        float acc[2][4][4];
#pragma unroll
        for (int mt = 0; mt < 2; mt++)
#pragma unroll
            for (int nt = 0; nt < 4; nt++)
#pragma unroll
                for (int r = 0; r < 4; r++) acc[mt][nt][r] = 0.f;

#pragma unroll
        for (int kc = 0; kc < 4; kc++) {
            const int kd = kc * 16 + 2 * tq + ((kc >= 2) ? 4 : 0);  // half1 at +36
            uint32_t ah[2][4], al[2][4];
#pragma unroll
            for (int mt = 0; mt < 2; mt++) {
                const float* p = Abuf + (EB + mt * 16 + gi) * A_STRIDE + kd;
                float2 f0 = *(const float2*)(p);
                float2 f1 = *(const float2*)(p + 8 * A_STRIDE);
                float2 f2 = *(const float2*)(p + 8);
                float2 f3 = *(const float2*)(p + 8 * A_STRIDE + 8);
                split_bf16(f0, ah[mt][0], al[mt][0]);
                split_bf16(f1, ah[mt][1], al[mt][1]);
                split_bf16(f2, ah[mt][2], al[mt][2]);
                split_bf16(f3, ah[mt][3], al[mt][3]);
            }
#pragma unroll
            for (int nt = 0; nt < 4; nt++) {
                const int col = NBASE + nt * 8 + gi;
                uint32_t bh[2], bl[2];
                bh[0] = Wh2[col * W_PAD + kc * 8 + tq];
                bh[1] = Wh2[col * W_PAD + kc * 8 + tq + 4];
                bl[0] = Wl2[col * W_PAD + kc * 8 + tq];
                bl[1] = Wl2[col * W_PAD + kc * 8 + tq + 4];
#pragma unroll
                for (int mt = 0; mt < 2; mt++) {
                    mma_bf16(acc[mt][nt], ah[mt], bh);
                    mma_bf16(acc[mt][nt], al[mt], bh);
                    mma_bf16(acc[mt][nt], ah[mt], bl);
                }
            }
        }

        // ---- scatter: thread owns logical couts NBASE+16p+4tq..+3 (v4) ----
        const int* oi = out_idx + (size_t)k * nE + ebase;
#pragma unroll
        for (int mt = 0; mt < 2; mt++) {
            const int r0 = EB + mt * 16 + gi;
            const int og0 = (ebase + r0 < nE) ? __ldg(oi + r0) : -1;
            const int og1 = (ebase + r0 + 8 < nE) ? __ldg(oi + r0 + 8) : -1;
#pragma unroll
            for (int p = 0; p < 2; p++) {
                const int cbase = NBASE + 16 * p + 4 * tq;
                if (og0 >= 0)
                    red_add_v4(yout + (size_t)og0 * 64 + cbase,
                               acc[mt][2 * p][0], acc[mt][2 * p][1],
                               acc[mt][2 * p + 1][0], acc[mt][2 * p + 1][1]);
                if (og1 >= 0)
                    red_add_v4(yout + (size_t)og1 * 64 + cbase,
                               acc[mt][2 * p][2], acc[mt][2 * p][3],
                               acc[mt][2 * p + 1][2], acc[mt][2 * p + 1][3]);
            }
        }
        __syncthreads();  // compute reads done -> buffer reusable next tile
    }
}

// ---------------------------------------------------------------------------
__global__ __launch_bounds__(256) void stats_kernel(const float* __restrict__ y,
                                                    float2* __restrict__ sums, int n) {
    const int lane = threadIdx.x & 31;
    const int warp = threadIdx.x >> 5;
    const int wpb = blockDim.x >> 5;

    float2 s = {0.f, 0.f}, q = {0.f, 0.f};
    for (int r = blockIdx.x * wpb + warp; r < n; r += gridDim.x * wpb) {
        float2 v = *(const float2*)(y + (size_t)r * 64 + 2 * lane);
        s.x += v.x; s.y += v.y;
        q.x = fmaf(v.x, v.x, q.x);
        q.y = fmaf(v.y, v.y, q.y);
    }
    __shared__ float2 sh_s[8][32], sh_q[8][32];
    sh_s[warp][lane] = s;
    sh_q[warp][lane] = q;
    __syncthreads();
    if (warp == 0) {
        for (int i = 1; i < wpb; i++) {
            s.x += sh_s[i][lane].x; s.y += sh_s[i][lane].y;
            q.x += sh_q[i][lane].x; q.y += sh_q[i][lane].y;
        }
        atomicAdd(&sums[lane], s);
        atomicAdd(&sums[32 + lane], q);
    }
}

__global__ void finalize_kernel(const float2* __restrict__ sums,
                                const float* __restrict__ gamma,
                                const float* __restrict__ beta,
                                float* __restrict__ bnout, float invN) {
    int l = threadIdx.x;  // 0..31 -> channels 2l, 2l+1
    float2 s = sums[l], q = sums[32 + l];
    float m0 = s.x * invN, m1 = s.y * invN;
    float v0 = fmaf(q.x, invN, -m0 * m0);
    float v1 = fmaf(q.y, invN, -m1 * m1);
    float sc0 = gamma[2 * l] * rsqrtf(v0 + 1e-5f);
    float sc1 = gamma[2 * l + 1] * rsqrtf(v1 + 1e-5f);
    bnout[2 * l] = sc0;
    bnout[2 * l + 1] = sc1;
    bnout[64 + 2 * l] = beta[2 * l] - m0 * sc0;
    bnout[64 + 2 * l + 1] = beta[2 * l + 1] - m1 * sc1;
}

__global__ __launch_bounds__(256) void final_kernel(const float4* __restrict__ y2,
                                                    const float4* __restrict__ x,
                                                    const float* __restrict__ bn,
                                                    float4* __restrict__ out, int n4) {
    int i = blockIdx.x * blockDim.x + threadIdx.x;
    if (i >= n4) return;
    int c4 = (i & 15) * 4;
    float4 v = y2[i], xr = x[i];
    float4 sc = *(const float4*)(bn + c4);
    float4 sh = *(const float4*)(bn + 64 + c4);
    float4 o;
    o.x = fmaxf(fmaf(v.x, sc.x, sh.x) + xr.x, 0.f);
    o.y = fmaxf(fmaf(v.y, sc.y, sh.y) + xr.y, 0.f);
    o.z = fmaxf(fmaf(v.z, sc.z, sh.z) + xr.z, 0.f);
    o.w = fmaxf(fmaf(v.w, sc.w, sh.w) + xr.w, 0.f);
    out[i] = o;
}

// ---------------------------------------------------------------------------
extern "C" void kernel_launch(void* const* d_in, const int* in_sizes, int n_in,
                              void* d_out, int out_size) {
    const float* x      = (const float*)d_in[0];
    const float* W1     = (const float*)d_in[2];
    const float* gamma1 = (const float*)d_in[3];
    const float* beta1  = (const float*)d_in[4];
    const float* W2     = (const float*)d_in[5];
    const float* gamma2 = (const float*)d_in[6];
    const float* beta2  = (const float*)d_in[7];
    const int* in_idx   = (const int*)d_in[8];
    const int* out_idx  = (const int*)d_in[9];

    const int N = in_sizes[0] / 64;
    const int K = in_sizes[2] / (64 * 64);

    float *y1, *y2, *bn;
    float2* stats;
    cudaGetSymbolAddress((void**)&y1, g_y1);
    cudaGetSymbolAddress((void**)&y2, g_y2);
    cudaGetSymbolAddress((void**)&stats, g_stats);
    cudaGetSymbolAddress((void**)&bn, g_bn);

    cudaFuncSetAttribute(conv_mma_kernel<false>,
                         cudaFuncAttributeMaxDynamicSharedMemorySize, SMEM_BYTES);
    cudaFuncSetAttribute(conv_mma_kernel<true>,
                         cudaFuncAttributeMaxDynamicSharedMemorySize, SMEM_BYTES);

    cudaMemsetAsync(y1, 0, (size_t)N * 64 * sizeof(float));
    cudaMemsetAsync(y2, 0, (size_t)N * 64 * sizeof(float));
    cudaMemsetAsync(stats, 0, 4 * 32 * sizeof(float2));

    const int NB = 296;  // 2 CTAs per SM
    const float invN = 1.0f / (float)N;

    // layer 1
    conv_mma_kernel<false><<<NB, 256, SMEM_BYTES>>>(x, W1, in_idx, out_idx, y1,
                                                    nullptr, N, K, NB);
    stats_kernel<<<256, 256>>>(y1, stats, N);
    finalize_kernel<<<1, 32>>>(stats, gamma1, beta1, bn, invN);

    // layer 2 (BN1 + ReLU folded into gather)
    conv_mma_kernel<true><<<NB, 256, SMEM_BYTES>>>(y1, W2, in_idx, out_idx, y2,
                                                   bn, N, K, NB);
    stats_kernel<<<256, 256>>>(y2, stats + 64, N);
    finalize_kernel<<<1, 32>>>(stats + 64, gamma2, beta2, bn + 128, invN);

    // epilogue: BN2 + residual + ReLU
    final_kernel<<<(N * 16 + 255) / 256, 256>>>((const float4*)y2, (const float4*)x,
                                                bn + 128, (float4*)d_out, N * 16);
}

// round 11
// speedup vs baseline: 1.3696x; 1.3696x over previous
#include <cuda_runtime.h>
#include <cuda_bf16.h>
#include <cstdint>

// ============================================================================
// ResidualBlockWithPointsBase — mma.sync BF16 3-pass + balanced hybrid gather
//   y1 = conv(x, W1); BN1 fold; y1a = relu(bn1(y1));
//   y2 = conv(y1a, W2); BN2 fold; out = relu(bn2(y2) + x)
// conv: persistent CTAs over (k, 128-edge tile), double-buffered gather:
//   rows  0..79  cp.async.bulk (TMA engine, mbarrier complete_tx)
//   rows 80..127 cp.async 16B  (L1 path, wait_group)
// -> in-register bf16 hi/lo split -> warp mma.m16n8k16 (3-term),
//   W pre-split bf16x2 smem (pad-36) -> red.global.add.v4.f32 scatter
//   (column-permuted). 2 CTAs/SM.
// ============================================================================

#define MAXN 100352

__device__ float g_y1[MAXN * 64];
__device__ float g_y1a[MAXN * 64];
__device__ float g_y2[MAXN * 64];
__device__ float2 g_stats[4 * 32];
__device__ float g_bn[4 * 64];

__device__ __forceinline__ void mma_bf16(float* d, const uint32_t* a, const uint32_t* b) {
    asm volatile(
        "mma.sync.aligned.m16n8k16.row.col.f32.bf16.bf16.f32 "
        "{%0,%1,%2,%3}, {%4,%5,%6,%7}, {%8,%9}, {%0,%1,%2,%3};"
        : "+f"(d[0]), "+f"(d[1]), "+f"(d[2]), "+f"(d[3])
        : "r"(a[0]), "r"(a[1]), "r"(a[2]), "r"(a[3]), "r"(b[0]), "r"(b[1]));
}
__device__ __forceinline__ void red_add_v4(float* g, float a, float b, float c, float d) {
    asm volatile("red.global.add.v4.f32 [%0], {%1, %2, %3, %4};"
                 :: "l"(g), "f"(a), "f"(b), "f"(c), "f"(d) : "memory");
}
// split float2 (f.x = even k, f.y = odd k) into bf16x2 hi and lo
__device__ __forceinline__ void split_bf16(float2 f, uint32_t& h, uint32_t& l) {
    __nv_bfloat162 hb = __floats2bfloat162_rn(f.x, f.y);
    float hx = __bfloat162float(__low2bfloat16(hb));
    float hy = __bfloat162float(__high2bfloat16(hb));
    __nv_bfloat162 lb = __floats2bfloat162_rn(f.x - hx, f.y - hy);
    h = *reinterpret_cast<uint32_t*>(&hb);
    l = *reinterpret_cast<uint32_t*>(&lb);
}

#define CP_ASYNC16(dst, src) \
    asm volatile("cp.async.ca.shared.global [%0], [%1], 16;" :: "r"(dst), "l"(src))
#define CP_COMMIT() asm volatile("cp.async.commit_group;" ::: "memory")
#define CP_WAIT1() asm volatile("cp.async.wait_group 1;" ::: "memory")
#define CP_WAIT0() asm volatile("cp.async.wait_group 0;" ::: "memory")

#define MBAR_WAIT(a, ph) do {                                                     \
    asm volatile("{\n\t.reg .pred P1;\n\tWL_%=:\n\t"                              \
        "mbarrier.try_wait.parity.acquire.cta.shared::cta.b64 P1, [%0], %1, 0x989680;\n\t" \
        "@P1 bra.uni WD_%=;\n\tbra.uni WL_%=;\n\tWD_%=:\n\t}"                     \
        :: "r"(a), "r"(ph) : "memory");                                           \
} while (0)

// smem layout (floats)
#define A_PAD 72                              // row stride; rows contiguous 64 floats
#define OFF_A0 0
#define OFF_A1 (128 * A_PAD)                  // 9216
#define OFF_W (2 * 128 * A_PAD)               // 18432
#define W_PAD 36
#define OFF_MBAR (OFF_W + 2 * 64 * W_PAD)     // 23040 floats
#define SMEM_FLOATS (OFF_MBAR + 4)
#define SMEM_BYTES (SMEM_FLOATS * 4)          // 92176

#define TMA_ROWS 80
#define TMA_BYTES (TMA_ROWS * 256u)           // 20480 expect_tx

// ---------------------------------------------------------------------------
__global__ __launch_bounds__(256, 2) void conv_mma_kernel(
    const float* __restrict__ xin,  // [N][64]
    const float* __restrict__ W,    // [K][64][64]
    const int* __restrict__ in_idx, const int* __restrict__ out_idx,
    float* __restrict__ yout,       // [N][64] pre-zeroed
    int nE, int K, int nblk) {
    extern __shared__ float sm[];
    uint32_t* Wh2 = (uint32_t*)(sm + OFF_W);
    uint32_t* Wl2 = Wh2 + 64 * W_PAD;
    const uint32_t smb = (uint32_t)__cvta_generic_to_shared(sm);

    const int tid = threadIdx.x;
    const int lane = tid & 31;
    const int wid = tid >> 5;
    const int gi = lane >> 2;
    const int tq = lane & 3;
    const int EB = (wid >> 1) * 32;    // warp's edge base
    const int NBASE = (wid & 1) * 32;  // warp's cout base

    const int tilesPerK = (nE + 127) >> 7;
    const int total = K * tilesPerK;
    const int chunk = (total + nblk - 1) / nblk;
    const int it0 = blockIdx.x * chunk;
    const int it1 = min(it0 + chunk, total);
    if (it0 >= it1) return;

    if (tid == 0) {
        asm volatile("mbarrier.init.shared.b64 [%0], 1;" :: "r"(smb + 4 * OFF_MBAR) : "memory");
        asm volatile("mbarrier.init.shared.b64 [%0], 1;" :: "r"(smb + 4 * OFF_MBAR + 8) : "memory");
        asm volatile("fence.proxy.async.shared::cta;" ::: "memory");
    }
    __syncthreads();

    // gather roles:
    //   tid   0..79  : TMA bulk, row = tid           (80 rows)
    //   tid 160..255 : cp.async 16B, row = 80 + (tid-160)/2, half = (tid-160)&1
    const bool is_tma = (tid < TMA_ROWS);
    const bool is_lsu = (tid >= 160);
    const int grow = is_tma ? tid : (is_lsu ? (TMA_ROWS + ((tid - 160) >> 1)) : 0);
    const int ghalf = (tid - 160) & 1;

    auto load_idx = [&](int item) -> int {
        int k = item / tilesPerK;
        int e = (item - k * tilesPerK) * 128 + grow;
        return (e < nE) ? __ldg(in_idx + (size_t)k * nE + e) : 0;
    };
    auto issue = [&](int item, int src_row) {
        const uint32_t st = (uint32_t)(item & 1);
        const uint32_t mb = smb + 4 * OFF_MBAR + 8 * st;
        const uint32_t abase = smb + 4 * (st ? OFF_A1 : OFF_A0);
        if (tid == 0)
            asm volatile("mbarrier.arrive.expect_tx.shared.b64 _, [%0], %1;"
                         :: "r"(mb), "r"(TMA_BYTES) : "memory");
        if (is_tma) {
            const float* src = xin + (size_t)src_row * 64;
            uint32_t dst = abase + (uint32_t)grow * (A_PAD * 4);
            asm volatile(
                "cp.async.bulk.shared::cluster.global.mbarrier::complete_tx::bytes "
                "[%0], [%1], %2, [%3];"
                :: "r"(dst), "l"(src), "r"(256u), "r"(mb) : "memory");
        } else if (is_lsu) {
            const float* src = xin + (size_t)src_row * 64 + ghalf * 32;
            uint32_t dst = abase + 4u * ((uint32_t)grow * A_PAD + ghalf * 32);
#pragma unroll
            for (int j = 0; j < 8; j++) CP_ASYNC16(dst + j * 16, src + j * 4);
        }
        CP_COMMIT();
    };

    int cur_k = -1;
    uint32_t ph0 = 0, ph1 = 0;

    int nidx = load_idx(it0);
    issue(it0, nidx);
    nidx = (it0 + 1 < it1) ? load_idx(it0 + 1) : 0;

    for (int item = it0; item < it1; item++) {
        const int k = item / tilesPerK;
        const int tile = item - k * tilesPerK;
        const int ebase = tile * 128;
        const int st = item & 1;

        if (item + 1 < it1) {
            issue(item + 1, nidx);
            nidx = (item + 2 < it1) ? load_idx(item + 2) : 0;
            CP_WAIT1();
        } else {
            CP_WAIT0();
        }

        if (k != cur_k) {  // W restage: bf16 hi/lo, k-pairs packed, col-permuted
            cur_k = k;
            const float* Wk = W + (size_t)k * 4096;
            for (int i = tid; i < 2048; i += 256) {
                int colP = i >> 5, j = i & 31;  // j = k-pair (k = 2j, 2j+1)
                int l16 = colP & 15;
                // inverse column permutation (for v4 scatter)
                int Lcol = (colP & ~15) + 4 * ((l16 >> 1) & 3) + 2 * ((l16 >> 3) & 1) + (l16 & 1);
                float w0 = __ldg(Wk + (size_t)(2 * j) * 64 + Lcol);
                float w1 = __ldg(Wk + (size_t)(2 * j + 1) * 64 + Lcol);
                uint32_t h, l;
                split_bf16(make_float2(w0, w1), h, l);
                Wh2[colP * W_PAD + j] = h;
                Wl2[colP * W_PAD + j] = l;
            }
        }

        // wait for this tile's TMA half, then make everything visible CTA-wide
        MBAR_WAIT(smb + 4 * OFF_MBAR + 8 * st, st ? ph1 : ph0);
        if (st) ph1 ^= 1; else ph0 ^= 1;
        __syncthreads();

        const float* Abuf = sm + (st ? OFF_A1 : OFF_A0);

        // ---- compute: 2 m-tiles x 4 n-tiles, 4 k-chunks (k=16), 3 terms ----
        float acc[2][4][4];
#pragma unroll
        for (int mt = 0; mt < 2; mt++)
#pragma unroll
            for (int nt = 0; nt < 4; nt++)
#pragma unroll
                for (int r = 0; r < 4; r++) acc[mt][nt][r] = 0.f;

#pragma unroll
        for (int kc = 0; kc < 4; kc++) {
            uint32_t ah[2][4], al[2][4];
#pragma unroll
            for (int mt = 0; mt < 2; mt++) {
                const float* p = Abuf + (EB + mt * 16 + gi) * A_PAD + kc * 16 + 2 * tq;
                float2 f0 = *(const float2*)(p);
                float2 f1 = *(const float2*)(p + 8 * A_PAD);
                float2 f2 = *(const float2*)(p + 8);
                float2 f3 = *(const float2*)(p + 8 * A_PAD + 8);
                split_bf16(f0, ah[mt][0], al[mt][0]);
                split_bf16(f1, ah[mt][1], al[mt][1]);
                split_bf16(f2, ah[mt][2], al[mt][2]);
                split_bf16(f3, ah[mt][3], al[mt][3]);
            }
#pragma unroll
            for (int nt = 0; nt < 4; nt++) {
                const int col = NBASE + nt * 8 + gi;
                uint32_t bh[2], bl[2];
                bh[0] = Wh2[col * W_PAD + kc * 8 + tq];
                bh[1] = Wh2[col * W_PAD + kc * 8 + tq + 4];
                bl[0] = Wl2[col * W_PAD + kc * 8 + tq];
                bl[1] = Wl2[col * W_PAD + kc * 8 + tq + 4];
#pragma unroll
                for (int mt = 0; mt < 2; mt++) {
                    mma_bf16(acc[mt][nt], ah[mt], bh);
                    mma_bf16(acc[mt][nt], al[mt], bh);
                    mma_bf16(acc[mt][nt], ah[mt], bl);
                }
            }
        }

        // ---- scatter: thread owns logical couts NBASE+16p+4tq..+3 (v4) ----
        const int* oi = out_idx + (size_t)k * nE + ebase;
#pragma unroll
        for (int mt = 0; mt < 2; mt++) {
            const int r0 = EB + mt * 16 + gi;
            const int og0 = (ebase + r0 < nE) ? __ldg(oi + r0) : -1;
            const int og1 = (ebase + r0 + 8 < nE) ? __ldg(oi + r0 + 8) : -1;
#pragma unroll
            for (int p = 0; p < 2; p++) {
                const int cbase = NBASE + 16 * p + 4 * tq;
                if (og0 >= 0)
                    red_add_v4(yout + (size_t)og0 * 64 + cbase,
                               acc[mt][2 * p][0], acc[mt][2 * p][1],
                               acc[mt][2 * p + 1][0], acc[mt][2 * p + 1][1]);
                if (og1 >= 0)
                    red_add_v4(yout + (size_t)og1 * 64 + cbase,
                               acc[mt][2 * p][2], acc[mt][2 * p][3],
                               acc[mt][2 * p + 1][2], acc[mt][2 * p + 1][3]);
            }
        }
        __syncthreads();  // all reads of stage st done -> safe to re-issue into it
    }
}

// ---------------------------------------------------------------------------
__global__ __launch_bounds__(256) void stats_kernel(const float* __restrict__ y,
                                                    float2* __restrict__ sums, int n) {
    const int lane = threadIdx.x & 31;
    const int warp = threadIdx.x >> 5;
    const int wpb = blockDim.x >> 5;

    float2 s = {0.f, 0.f}, q = {0.f, 0.f};
    for (int r = blockIdx.x * wpb + warp; r < n; r += gridDim.x * wpb) {
        float2 v = *(const float2*)(y + (size_t)r * 64 + 2 * lane);
        s.x += v.x; s.y += v.y;
        q.x = fmaf(v.x, v.x, q.x);
        q.y = fmaf(v.y, v.y, q.y);
    }
    __shared__ float2 sh_s[8][32], sh_q[8][32];
    sh_s[warp][lane] = s;
    sh_q[warp][lane] = q;
    __syncthreads();
    if (warp == 0) {
        for (int i = 1; i < wpb; i++) {
            s.x += sh_s[i][lane].x; s.y += sh_s[i][lane].y;
            q.x += sh_q[i][lane].x; q.y += sh_q[i][lane].y;
        }
        atomicAdd(&sums[lane], s);
        atomicAdd(&sums[32 + lane], q);
    }
}

__global__ void finalize_kernel(const float2* __restrict__ sums,
                                const float* __restrict__ gamma,
                                const float* __restrict__ beta,
                                float* __restrict__ bnout, float invN) {
    int l = threadIdx.x;  // 0..31 -> channels 2l, 2l+1
    float2 s = sums[l], q = sums[32 + l];
    float m0 = s.x * invN, m1 = s.y * invN;
    float v0 = fmaf(q.x, invN, -m0 * m0);
    float v1 = fmaf(q.y, invN, -m1 * m1);
    float sc0 = gamma[2 * l] * rsqrtf(v0 + 1e-5f);
    float sc1 = gamma[2 * l + 1] * rsqrtf(v1 + 1e-5f);
    bnout[2 * l] = sc0;
    bnout[2 * l + 1] = sc1;
    bnout[64 + 2 * l] = beta[2 * l] - m0 * sc0;
    bnout[64 + 2 * l + 1] = beta[2 * l + 1] - m1 * sc1;
}

// y1a = relu(bn1(y1))
__global__ __launch_bounds__(256) void apply_bn_kernel(const float4* __restrict__ y,
                                                       const float* __restrict__ bn,
                                                       float4* __restrict__ out, int n4) {
    int i = blockIdx.x * blockDim.x + threadIdx.x;
    if (i >= n4) return;
    int c4 = (i & 15) * 4;
    float4 v = y[i];
    float4 sc = *(const float4*)(bn + c4);
    float4 sh = *(const float4*)(bn + 64 + c4);
    float4 o;
    o.x = fmaxf(fmaf(v.x, sc.x, sh.x), 0.f);
    o.y = fmaxf(fmaf(v.y, sc.y, sh.y), 0.f);
    o.z = fmaxf(fmaf(v.z, sc.z, sh.z), 0.f);
    o.w = fmaxf(fmaf(v.w, sc.w, sh.w), 0.f);
    out[i] = o;
}

__global__ __launch_bounds__(256) void final_kernel(const float4* __restrict__ y2,
                                                    const float4* __restrict__ x,
                                                    const float* __restrict__ bn,
                                                    float4* __restrict__ out, int n4) {
    int i = blockIdx.x * blockDim.x + threadIdx.x;
    if (i >= n4) return;
    int c4 = (i & 15) * 4;
    float4 v = y2[i], xr = x[i];
    float4 sc = *(const float4*)(bn + c4);
    float4 sh = *(const float4*)(bn + 64 + c4);
    float4 o;
    o.x = fmaxf(fmaf(v.x, sc.x, sh.x) + xr.x, 0.f);
    o.y = fmaxf(fmaf(v.y, sc.y, sh.y) + xr.y, 0.f);
    o.z = fmaxf(fmaf(v.z, sc.z, sh.z) + xr.z, 0.f);
    o.w = fmaxf(fmaf(v.w, sc.w, sh.w) + xr.w, 0.f);
    out[i] = o;
}

// ---------------------------------------------------------------------------
extern "C" void kernel_launch(void* const* d_in, const int* in_sizes, int n_in,
                              void* d_out, int out_size) {
    const float* x      = (const float*)d_in[0];
    const float* W1     = (const float*)d_in[2];
    const float* gamma1 = (const float*)d_in[3];
    const float* beta1  = (const float*)d_in[4];
    const float* W2     = (const float*)d_in[5];
    const float* gamma2 = (const float*)d_in[6];
    const float* beta2  = (const float*)d_in[7];
    const int* in_idx   = (const int*)d_in[8];
    const int* out_idx  = (const int*)d_in[9];

    const int N = in_sizes[0] / 64;
    const int K = in_sizes[2] / (64 * 64);

    float *y1, *y1a, *y2, *bn;
    float2* stats;
    cudaGetSymbolAddress((void**)&y1, g_y1);
    cudaGetSymbolAddress((void**)&y1a, g_y1a);
    cudaGetSymbolAddress((void**)&y2, g_y2);
    cudaGetSymbolAddress((void**)&stats, g_stats);
    cudaGetSymbolAddress((void**)&bn, g_bn);

    cudaFuncSetAttribute(conv_mma_kernel,
                         cudaFuncAttributeMaxDynamicSharedMemorySize, SMEM_BYTES);

    cudaMemsetAsync(y1, 0, (size_t)N * 64 * sizeof(float));
    cudaMemsetAsync(y2, 0, (size_t)N * 64 * sizeof(float));
    cudaMemsetAsync(stats, 0, 4 * 32 * sizeof(float2));

    const int NB = 296;  // 2 CTAs per SM
    const float invN = 1.0f / (float)N;

    // layer 1
    conv_mma_kernel<<<NB, 256, SMEM_BYTES>>>(x, W1, in_idx, out_idx, y1, N, K, NB);
    stats_kernel<<<256, 256>>>(y1, stats, N);
    finalize_kernel<<<1, 32>>>(stats, gamma1, beta1, bn, invN);
    apply_bn_kernel<<<(N * 16 + 255) / 256, 256>>>((const float4*)y1, bn, (float4*)y1a, N * 16);

    // layer 2
    conv_mma_kernel<<<NB, 256, SMEM_BYTES>>>(y1a, W2, in_idx, out_idx, y2, N, K, NB);
    stats_kernel<<<256, 256>>>(y2, stats + 64, N);
    finalize_kernel<<<1, 32>>>(stats + 64, gamma2, beta2, bn + 128, invN);

    // epilogue
    final_kernel<<<(N * 16 + 255) / 256, 256>>>((const float4*)y2, (const float4*)x,
                                                bn + 128, (float4*)d_out, N * 16);
}

// round 12
// speedup vs baseline: 1.5591x; 1.1383x over previous
#include <cuda_runtime.h>
#include <cuda_bf16.h>
#include <cstdint>

// ============================================================================
// ResidualBlockWithPointsBase — BF16 3-pass mma.sync, pre-split operands
//   xc  = split_bf16(x)                    [elementwise]
//   y1  = conv(xc, W1); BN1 fold
//   y1c = split_bf16(relu(bn1(y1)))        [elementwise, BN folded]
//   y2  = conv(y1c, W2); BN2 fold
//   out = relu(bn2(y2) + x)
// conv: persistent CTAs over (k, 128-edge tile), double-buffered all-TMA
//   gather (256B/row = [hi 64bf16][lo 64bf16]), W-hi fragments cached in
//   registers per k, W-lo in smem, warp mma.m16n8k16 3-term,
//   red.global.add.v4.f32 scatter (column-permuted). 2 CTAs/SM.
// ============================================================================

#define MAXN 100352

__device__ uint32_t g_xc[MAXN * 64];   // [row][hi pairs 0..31 | lo pairs 32..63]
__device__ uint32_t g_y1c[MAXN * 64];
__device__ float g_y1[MAXN * 64];
__device__ float g_y2[MAXN * 64];
__device__ float2 g_stats[4 * 32];
__device__ float g_bn[4 * 64];

__device__ __forceinline__ void mma_bf16(float* d, const uint32_t* a, const uint32_t* b) {
    asm volatile(
        "mma.sync.aligned.m16n8k16.row.col.f32.bf16.bf16.f32 "
        "{%0,%1,%2,%3}, {%4,%5,%6,%7}, {%8,%9}, {%0,%1,%2,%3};"
        : "+f"(d[0]), "+f"(d[1]), "+f"(d[2]), "+f"(d[3])
        : "r"(a[0]), "r"(a[1]), "r"(a[2]), "r"(a[3]), "r"(b[0]), "r"(b[1]));
}
__device__ __forceinline__ void red_add_v4(float* g, float a, float b, float c, float d) {
    asm volatile("red.global.add.v4.f32 [%0], {%1, %2, %3, %4};"
                 :: "l"(g), "f"(a), "f"(b), "f"(c), "f"(d) : "memory");
}
// split float2 into bf16x2 hi and lo words
__device__ __forceinline__ void split_bf16(float2 f, uint32_t& h, uint32_t& l) {
    __nv_bfloat162 hb = __floats2bfloat162_rn(f.x, f.y);
    float hx = __bfloat162float(__low2bfloat16(hb));
    float hy = __bfloat162float(__high2bfloat16(hb));
    __nv_bfloat162 lb = __floats2bfloat162_rn(f.x - hx, f.y - hy);
    h = *reinterpret_cast<uint32_t*>(&hb);
    l = *reinterpret_cast<uint32_t*>(&lb);
}

#define MBAR_WAIT(a, ph) do {                                                     \
    asm volatile("{\n\t.reg .pred P1;\n\tWL_%=:\n\t"                              \
        "mbarrier.try_wait.parity.acquire.cta.shared::cta.b64 P1, [%0], %1, 0x989680;\n\t" \
        "@P1 bra.uni WD_%=;\n\tbra.uni WL_%=;\n\tWD_%=:\n\t}"                     \
        :: "r"(a), "r"(ph) : "memory");                                           \
} while (0)

// smem layout (u32 units)
#define A_STRIDE 68                            // 272B/row (16B aligned)
#define OFF_A0 0
#define OFF_A1 (128 * A_STRIDE)                // 8704
#define OFF_WH (2 * 128 * A_STRIDE)            // 17408
#define W_PAD 36
#define OFF_WL (OFF_WH + 64 * W_PAD)           // 19712
#define OFF_MBAR (OFF_WL + 64 * W_PAD)         // 22016 (byte 88064, 8B aligned)
#define SMEM_U32 (OFF_MBAR + 4)
#define SMEM_BYTES (SMEM_U32 * 4)              // 88080

#define TILE_BYTES 32768u  // 128 rows x 256B payload

// ---------------------------------------------------------------------------
__global__ __launch_bounds__(256, 2) void conv_mma_kernel(
    const uint32_t* __restrict__ xc,  // [N][64] u32 (hi 0..31, lo 32..63)
    const float* __restrict__ W,      // [K][64][64]
    const int* __restrict__ in_idx, const int* __restrict__ out_idx,
    float* __restrict__ yout,         // [N][64] pre-zeroed
    int nE, int K, int nblk) {
    extern __shared__ uint32_t sm[];
    uint32_t* Wh2 = sm + OFF_WH;
    uint32_t* Wl2 = sm + OFF_WL;
    const uint32_t smb = (uint32_t)__cvta_generic_to_shared(sm);

    const int tid = threadIdx.x;
    const int lane = tid & 31;
    const int wid = tid >> 5;
    const int gi = lane >> 2;
    const int tq = lane & 3;
    const int EB = (wid >> 1) * 32;    // warp's edge base
    const int NBASE = (wid & 1) * 32;  // warp's cout base

    const int tilesPerK = (nE + 127) >> 7;
    const int total = K * tilesPerK;
    const int chunk = (total + nblk - 1) / nblk;
    const int it0 = blockIdx.x * chunk;
    const int it1 = min(it0 + chunk, total);
    if (it0 >= it1) return;

    if (tid == 0) {
        asm volatile("mbarrier.init.shared.b64 [%0], 1;" :: "r"(smb + 4 * OFF_MBAR) : "memory");
        asm volatile("mbarrier.init.shared.b64 [%0], 1;" :: "r"(smb + 4 * OFF_MBAR + 8) : "memory");
        asm volatile("fence.proxy.async.shared::cta;" ::: "memory");
    }
    __syncthreads();

    auto load_idx = [&](int item) -> int {
        int k = item / tilesPerK;
        int e = (item - k * tilesPerK) * 128 + tid;
        return (e < nE) ? __ldg(in_idx + (size_t)k * nE + e) : 0;
    };
    auto issue = [&](int item, int src_row) {
        const uint32_t st = (uint32_t)(item & 1);
        const uint32_t mb = smb + 4 * OFF_MBAR + 8 * st;
        if (tid == 0)
            asm volatile("mbarrier.arrive.expect_tx.shared.b64 _, [%0], %1;"
                         :: "r"(mb), "r"(TILE_BYTES) : "memory");
        if (tid < 128) {
            const uint32_t* src = xc + (size_t)src_row * 64;
            uint32_t dst = smb + 4 * (st ? OFF_A1 : OFF_A0) + (uint32_t)tid * (A_STRIDE * 4);
            asm volatile(
                "cp.async.bulk.shared::cluster.global.mbarrier::complete_tx::bytes "
                "[%0], [%1], %2, [%3];"
                :: "r"(dst), "l"(src), "r"(256u), "r"(mb) : "memory");
        }
    };

    int cur_k = -1;
    uint32_t ph0 = 0, ph1 = 0;
    uint32_t BhR[4][4][2];  // W-hi fragments, register-resident per k

    int nidx = (tid < 128) ? load_idx(it0) : 0;
    issue(it0, nidx);
    nidx = (tid < 128 && it0 + 1 < it1) ? load_idx(it0 + 1) : 0;

    for (int item = it0; item < it1; item++) {
        const int k = item / tilesPerK;
        const int tile = item - k * tilesPerK;
        const int ebase = tile * 128;
        const int st = item & 1;

        if (item + 1 < it1) {
            issue(item + 1, nidx);
            nidx = (tid < 128 && item + 2 < it1) ? load_idx(item + 2) : 0;
        }

        if (k != cur_k) {  // W restage (smem) + reload W-hi fragments into regs
            cur_k = k;
            const float* Wk = W + (size_t)k * 4096;
            for (int i = tid; i < 2048; i += 256) {
                int colP = i >> 5, j = i & 31;  // j = k-pair (k = 2j, 2j+1)
                int l16 = colP & 15;
                // inverse column permutation (for v4 scatter)
                int Lcol = (colP & ~15) + 4 * ((l16 >> 1) & 3) + 2 * ((l16 >> 3) & 1) + (l16 & 1);
                float w0 = __ldg(Wk + (size_t)(2 * j) * 64 + Lcol);
                float w1 = __ldg(Wk + (size_t)(2 * j + 1) * 64 + Lcol);
                uint32_t h, l;
                split_bf16(make_float2(w0, w1), h, l);
                Wh2[colP * W_PAD + j] = h;
                Wl2[colP * W_PAD + j] = l;
            }
            __syncthreads();
#pragma unroll
            for (int nt = 0; nt < 4; nt++) {
                const int col = NBASE + nt * 8 + gi;
#pragma unroll
                for (int kc = 0; kc < 4; kc++) {
                    BhR[nt][kc][0] = Wh2[col * W_PAD + kc * 8 + tq];
                    BhR[nt][kc][1] = Wh2[col * W_PAD + kc * 8 + tq + 4];
                }
            }
        }

        // wait for this tile's gather
        MBAR_WAIT(smb + 4 * OFF_MBAR + 8 * st, st ? ph1 : ph0);
        if (st) ph1 ^= 1; else ph0 ^= 1;
        __syncthreads();

        const uint32_t* Abuf = sm + (st ? OFF_A1 : OFF_A0);

        // ---- compute: 2 m-tiles x 4 n-tiles, 4 k-chunks (k=16), 3 terms ----
        float acc[2][4][4];
#pragma unroll
        for (int mt = 0; mt < 2; mt++)
#pragma unroll
            for (int nt = 0; nt < 4; nt++)
#pragma unroll
                for (int r = 0; r < 4; r++) acc[mt][nt][r] = 0.f;

#pragma unroll
        for (int kc = 0; kc < 4; kc++) {
            uint32_t ah[2][4], al[2][4];
#pragma unroll
            for (int mt = 0; mt < 2; mt++) {
                const uint32_t* p = Abuf + (EB + mt * 16 + gi) * A_STRIDE + kc * 8 + tq;
                ah[mt][0] = p[0];
                ah[mt][1] = p[8 * A_STRIDE];
                ah[mt][2] = p[4];
                ah[mt][3] = p[8 * A_STRIDE + 4];
                al[mt][0] = p[32];
                al[mt][1] = p[8 * A_STRIDE + 32];
                al[mt][2] = p[36];
                al[mt][3] = p[8 * A_STRIDE + 36];
            }
#pragma unroll
            for (int nt = 0; nt < 4; nt++) {
                const int col = NBASE + nt * 8 + gi;
                uint32_t bl[2];
                bl[0] = Wl2[col * W_PAD + kc * 8 + tq];
                bl[1] = Wl2[col * W_PAD + kc * 8 + tq + 4];
#pragma unroll
                for (int mt = 0; mt < 2; mt++) {
                    mma_bf16(acc[mt][nt], ah[mt], BhR[nt][kc]);
                    mma_bf16(acc[mt][nt], al[mt], BhR[nt][kc]);
                    mma_bf16(acc[mt][nt], ah[mt], bl);
                }
            }
        }

        // ---- scatter: thread owns logical couts NBASE+16p+4tq..+3 (v4) ----
        const int* oi = out_idx + (size_t)k * nE + ebase;
#pragma unroll
        for (int mt = 0; mt < 2; mt++) {
            const int r0 = EB + mt * 16 + gi;
            const int og0 = (ebase + r0 < nE) ? __ldg(oi + r0) : -1;
            const int og1 = (ebase + r0 + 8 < nE) ? __ldg(oi + r0 + 8) : -1;
#pragma unroll
            for (int p = 0; p < 2; p++) {
                const int cbase = NBASE + 16 * p + 4 * tq;
                if (og0 >= 0)
                    red_add_v4(yout + (size_t)og0 * 64 + cbase,
                               acc[mt][2 * p][0], acc[mt][2 * p][1],
                               acc[mt][2 * p + 1][0], acc[mt][2 * p + 1][1]);
                if (og1 >= 0)
                    red_add_v4(yout + (size_t)og1 * 64 + cbase,
                               acc[mt][2 * p][2], acc[mt][2 * p][3],
                               acc[mt][2 * p + 1][2], acc[mt][2 * p + 1][3]);
            }
        }
        __syncthreads();  // all reads of stage st done -> safe to re-issue into it
    }
}

// ---------------------------------------------------------------------------
// xc[row] = bf16 hi/lo split of (optionally BN+ReLU of) src row.
// thread j of row r handles channels (2j, 2j+1) -> hi word r*64+j, lo +32.
template <bool BN>
__global__ __launch_bounds__(256) void convert_kernel(const float2* __restrict__ src,
                                                      uint32_t* __restrict__ dst,
                                                      const float* __restrict__ bnp,
                                                      int n32) {
    int i = blockIdx.x * blockDim.x + threadIdx.x;
    if (i >= n32) return;
    int j = i & 31, row = i >> 5;
    float2 v = src[i];
    if (BN) {
        float2 sc = *(const float2*)(bnp + 2 * j);
        float2 sh = *(const float2*)(bnp + 64 + 2 * j);
        v.x = fmaxf(fmaf(v.x, sc.x, sh.x), 0.f);
        v.y = fmaxf(fmaf(v.y, sc.y, sh.y), 0.f);
    }
    uint32_t h, l;
    split_bf16(v, h, l);
    dst[(size_t)row * 64 + j] = h;
    dst[(size_t)row * 64 + 32 + j] = l;
}

// ---------------------------------------------------------------------------
__global__ __launch_bounds__(256) void stats_kernel(const float* __restrict__ y,
                                                    float2* __restrict__ sums, int n) {
    const int lane = threadIdx.x & 31;
    const int warp = threadIdx.x >> 5;
    const int wpb = blockDim.x >> 5;

    float2 s = {0.f, 0.f}, q = {0.f, 0.f};
    for (int r = blockIdx.x * wpb + warp; r < n; r += gridDim.x * wpb) {
        float2 v = *(const float2*)(y + (size_t)r * 64 + 2 * lane);
        s.x += v.x; s.y += v.y;
        q.x = fmaf(v.x, v.x, q.x);
        q.y = fmaf(v.y, v.y, q.y);
    }
    __shared__ float2 sh_s[8][32], sh_q[8][32];
    sh_s[warp][lane] = s;
    sh_q[warp][lane] = q;
    __syncthreads();
    if (warp == 0) {
        for (int i = 1; i < wpb; i++) {
            s.x += sh_s[i][lane].x; s.y += sh_s[i][lane].y;
            q.x += sh_q[i][lane].x; q.y += sh_q[i][lane].y;
        }
        atomicAdd(&sums[lane], s);
        atomicAdd(&sums[32 + lane], q);
    }
}

__global__ void finalize_kernel(const float2* __restrict__ sums,
                                const float* __restrict__ gamma,
                                const float* __restrict__ beta,
                                float* __restrict__ bnout, float invN) {
    int l = threadIdx.x;  // 0..31 -> channels 2l, 2l+1
    float2 s = sums[l], q = sums[32 + l];
    float m0 = s.x * invN, m1 = s.y * invN;
    float v0 = fmaf(q.x, invN, -m0 * m0);
    float v1 = fmaf(q.y, invN, -m1 * m1);
    float sc0 = gamma[2 * l] * rsqrtf(v0 + 1e-5f);
    float sc1 = gamma[2 * l + 1] * rsqrtf(v1 + 1e-5f);
    bnout[2 * l] = sc0;
    bnout[2 * l + 1] = sc1;
    bnout[64 + 2 * l] = beta[2 * l] - m0 * sc0;
    bnout[64 + 2 * l + 1] = beta[2 * l + 1] - m1 * sc1;
}

__global__ __launch_bounds__(256) void final_kernel(const float4* __restrict__ y2,
                                                    const float4* __restrict__ x,
                                                    const float* __restrict__ bn,
                                                    float4* __restrict__ out, int n4) {
    int i = blockIdx.x * blockDim.x + threadIdx.x;
    if (i >= n4) return;
    int c4 = (i & 15) * 4;
    float4 v = y2[i], xr = x[i];
    float4 sc = *(const float4*)(bn + c4);
    float4 sh = *(const float4*)(bn + 64 + c4);
    float4 o;
    o.x = fmaxf(fmaf(v.x, sc.x, sh.x) + xr.x, 0.f);
    o.y = fmaxf(fmaf(v.y, sc.y, sh.y) + xr.y, 0.f);
    o.z = fmaxf(fmaf(v.z, sc.z, sh.z) + xr.z, 0.f);
    o.w = fmaxf(fmaf(v.w, sc.w, sh.w) + xr.w, 0.f);
    out[i] = o;
}

// ---------------------------------------------------------------------------
extern "C" void kernel_launch(void* const* d_in, const int* in_sizes, int n_in,
                              void* d_out, int out_size) {
    const float* x      = (const float*)d_in[0];
    const float* W1     = (const float*)d_in[2];
    const float* gamma1 = (const float*)d_in[3];
    const float* beta1  = (const float*)d_in[4];
    const float* W2     = (const float*)d_in[5];
    const float* gamma2 = (const float*)d_in[6];
    const float* beta2  = (const float*)d_in[7];
    const int* in_idx   = (const int*)d_in[8];
    const int* out_idx  = (const int*)d_in[9];

    const int N = in_sizes[0] / 64;
    const int K = in_sizes[2] / (64 * 64);

    float *y1, *y2, *bn;
    uint32_t *xc, *y1c;
    float2* stats;
    cudaGetSymbolAddress((void**)&xc, g_xc);
    cudaGetSymbolAddress((void**)&y1c, g_y1c);
    cudaGetSymbolAddress((void**)&y1, g_y1);
    cudaGetSymbolAddress((void**)&y2, g_y2);
    cudaGetSymbolAddress((void**)&stats, g_stats);
    cudaGetSymbolAddress((void**)&bn, g_bn);

    cudaFuncSetAttribute(conv_mma_kernel,
                         cudaFuncAttributeMaxDynamicSharedMemorySize, SMEM_BYTES);

    cudaMemsetAsync(y1, 0, (size_t)N * 64 * sizeof(float));
    cudaMemsetAsync(y2, 0, (size_t)N * 64 * sizeof(float));
    cudaMemsetAsync(stats, 0, 4 * 32 * sizeof(float2));

    const int NB = 296;  // 2 CTAs per SM
    const float invN = 1.0f / (float)N;
    const int n32 = N * 32;

    // layer 1
    convert_kernel<false><<<(n32 + 255) / 256, 256>>>((const float2*)x, xc, nullptr, n32);
    conv_mma_kernel<<<NB, 256, SMEM_BYTES>>>(xc, W1, in_idx, out_idx, y1, N, K, NB);
    stats_kernel<<<256, 256>>>(y1, stats, N);
    finalize_kernel<<<1, 32>>>(stats, gamma1, beta1, bn, invN);

    // layer 2 (BN1 + ReLU folded into the split)
    convert_kernel<true><<<(n32 + 255) / 256, 256>>>((const float2*)y1, y1c, bn, n32);
    conv_mma_kernel<<<NB, 256, SMEM_BYTES>>>(y1c, W2, in_idx, out_idx, y2, N, K, NB);
    stats_kernel<<<256, 256>>>(y2, stats + 64, N);
    finalize_kernel<<<1, 32>>>(stats + 64, gamma2, beta2, bn + 128, invN);

    // epilogue: BN2 + residual + ReLU
    final_kernel<<<(N * 16 + 255) / 256, 256>>>((const float4*)y2, (const float4*)x,
                                                bn + 128, (float4*)d_out, N * 16);
}

// round 13
// speedup vs baseline: 1.7138x; 1.0993x over previous
#include <cuda_runtime.h>
#include <cuda_fp16.h>
#include <cstdint>

// ============================================================================
// ResidualBlockWithPointsBase — FP16 2-term mma.sync, pre-split x, fp16 W
//   xc  = split_fp16(x)                    [elementwise: x = h + l exactly]
//   y1  = conv(xc, W1); BN1 fold
//   y1c = split_fp16(relu(bn1(y1)))        [elementwise, BN folded]
//   y2  = conv(y1c, W2); BN2 fold
//   out = relu(bn2(y2) + x)
// conv: persistent CTAs over (k, 128-edge tile), double-buffered all-TMA
//   gather (256B/row = [hi 64fp16][lo 64fp16]), W single fp16 cached in
//   registers per k (no W smem traffic in loop), warp mma.m16n8k16
//   2-term (Ah*B + Al*B), red.global.add.v4.f32 scatter (column-permuted).
//   2 CTAs/SM.
// ============================================================================

#define MAXN 100352

__device__ uint32_t g_xc[MAXN * 64];   // [row][hi pairs 0..31 | lo pairs 32..63]
__device__ uint32_t g_y1c[MAXN * 64];
__device__ float g_y1[MAXN * 64];
__device__ float g_y2[MAXN * 64];
__device__ float2 g_stats[4 * 32];
__device__ float g_bn[4 * 64];

__device__ __forceinline__ void mma_f16(float* d, const uint32_t* a, const uint32_t* b) {
    asm volatile(
        "mma.sync.aligned.m16n8k16.row.col.f32.f16.f16.f32 "
        "{%0,%1,%2,%3}, {%4,%5,%6,%7}, {%8,%9}, {%0,%1,%2,%3};"
        : "+f"(d[0]), "+f"(d[1]), "+f"(d[2]), "+f"(d[3])
        : "r"(a[0]), "r"(a[1]), "r"(a[2]), "r"(a[3]), "r"(b[0]), "r"(b[1]));
}
__device__ __forceinline__ void red_add_v4(float* g, float a, float b, float c, float d) {
    asm volatile("red.global.add.v4.f32 [%0], {%1, %2, %3, %4};"
                 :: "l"(g), "f"(a), "f"(b), "f"(c), "f"(d) : "memory");
}
// split float2 into fp16x2 hi and lo words (x = h + l to ~2^-23)
__device__ __forceinline__ void split_fp16(float2 f, uint32_t& h, uint32_t& l) {
    __half2 hb = __floats2half2_rn(f.x, f.y);
    float hx = __half2float(__low2half(hb));
    float hy = __half2float(__high2half(hb));
    __half2 lb = __floats2half2_rn(f.x - hx, f.y - hy);
    h = *reinterpret_cast<uint32_t*>(&hb);
    l = *reinterpret_cast<uint32_t*>(&lb);
}

#define MBAR_WAIT(a, ph) do {                                                     \
    asm volatile("{\n\t.reg .pred P1;\n\tWL_%=:\n\t"                              \
        "mbarrier.try_wait.parity.acquire.cta.shared::cta.b64 P1, [%0], %1, 0x989680;\n\t" \
        "@P1 bra.uni WD_%=;\n\tbra.uni WL_%=;\n\tWD_%=:\n\t}"                     \
        :: "r"(a), "r"(ph) : "memory");                                           \
} while (0)

// smem layout (u32 units)
#define A_STRIDE 68                            // 272B/row (16B aligned)
#define OFF_A0 0
#define OFF_A1 (128 * A_STRIDE)                // 8704
#define OFF_WH (2 * 128 * A_STRIDE)            // 17408
#define W_PAD 36
#define OFF_MBAR (OFF_WH + 64 * W_PAD)         // 19712 (byte 78848, 8B aligned)
#define SMEM_U32 (OFF_MBAR + 4)
#define SMEM_BYTES (SMEM_U32 * 4)              // 78864

#define TILE_BYTES 32768u  // 128 rows x 256B payload

// ---------------------------------------------------------------------------
__global__ __launch_bounds__(256, 2) void conv_mma_kernel(
    const uint32_t* __restrict__ xc,  // [N][64] u32 (hi 0..31, lo 32..63)
    const float* __restrict__ W,      // [K][64][64]
    const int* __restrict__ in_idx, const int* __restrict__ out_idx,
    float* __restrict__ yout,         // [N][64] pre-zeroed
    int nE, int K, int nblk) {
    extern __shared__ uint32_t sm[];
    uint32_t* Wh2 = sm + OFF_WH;
    const uint32_t smb = (uint32_t)__cvta_generic_to_shared(sm);

    const int tid = threadIdx.x;
    const int lane = tid & 31;
    const int wid = tid >> 5;
    const int gi = lane >> 2;
    const int tq = lane & 3;
    const int EB = (wid >> 1) * 32;    // warp's edge base
    const int NBASE = (wid & 1) * 32;  // warp's cout base

    const int tilesPerK = (nE + 127) >> 7;
    const int total = K * tilesPerK;
    const int chunk = (total + nblk - 1) / nblk;
    const int it0 = blockIdx.x * chunk;
    const int it1 = min(it0 + chunk, total);
    if (it0 >= it1) return;

    if (tid == 0) {
        asm volatile("mbarrier.init.shared.b64 [%0], 1;" :: "r"(smb + 4 * OFF_MBAR) : "memory");
        asm volatile("mbarrier.init.shared.b64 [%0], 1;" :: "r"(smb + 4 * OFF_MBAR + 8) : "memory");
        asm volatile("fence.proxy.async.shared::cta;" ::: "memory");
    }
    __syncthreads();

    auto load_idx = [&](int item) -> int {
        int k = item / tilesPerK;
        int e = (item - k * tilesPerK) * 128 + tid;
        return (e < nE) ? __ldg(in_idx + (size_t)k * nE + e) : 0;
    };
    auto issue = [&](int item, int src_row) {
        const uint32_t st = (uint32_t)(item & 1);
        const uint32_t mb = smb + 4 * OFF_MBAR + 8 * st;
        if (tid == 0)
            asm volatile("mbarrier.arrive.expect_tx.shared.b64 _, [%0], %1;"
                         :: "r"(mb), "r"(TILE_BYTES) : "memory");
        if (tid < 128) {
            const uint32_t* src = xc + (size_t)src_row * 64;
            uint32_t dst = smb + 4 * (st ? OFF_A1 : OFF_A0) + (uint32_t)tid * (A_STRIDE * 4);
            asm volatile(
                "cp.async.bulk.shared::cluster.global.mbarrier::complete_tx::bytes "
                "[%0], [%1], %2, [%3];"
                :: "r"(dst), "l"(src), "r"(256u), "r"(mb) : "memory");
        }
    };

    int cur_k = -1;
    uint32_t ph0 = 0, ph1 = 0;
    uint32_t BhR[4][4][2];  // W fp16 fragments, register-resident per k

    int nidx = (tid < 128) ? load_idx(it0) : 0;
    issue(it0, nidx);
    nidx = (tid < 128 && it0 + 1 < it1) ? load_idx(it0 + 1) : 0;

    for (int item = it0; item < it1; item++) {
        const int k = item / tilesPerK;
        const int tile = item - k * tilesPerK;
        const int ebase = tile * 128;
        const int st = item & 1;

        if (item + 1 < it1) {
            issue(item + 1, nidx);
            nidx = (tid < 128 && item + 2 < it1) ? load_idx(item + 2) : 0;
        }

        if (k != cur_k) {  // W restage (smem bounce) + load fragments into regs
            cur_k = k;
            const float* Wk = W + (size_t)k * 4096;
            for (int i = tid; i < 2048; i += 256) {
                int colP = i >> 5, j = i & 31;  // j = k-pair (k = 2j, 2j+1)
                int l16 = colP & 15;
                // inverse column permutation (for v4 scatter)
                int Lcol = (colP & ~15) + 4 * ((l16 >> 1) & 3) + 2 * ((l16 >> 3) & 1) + (l16 & 1);
                float w0 = __ldg(Wk + (size_t)(2 * j) * 64 + Lcol);
                float w1 = __ldg(Wk + (size_t)(2 * j + 1) * 64 + Lcol);
                __half2 w2 = __floats2half2_rn(w0, w1);
                Wh2[colP * W_PAD + j] = *reinterpret_cast<uint32_t*>(&w2);
            }
            __syncthreads();
#pragma unroll
            for (int nt = 0; nt < 4; nt++) {
                const int col = NBASE + nt * 8 + gi;
#pragma unroll
                for (int kc = 0; kc < 4; kc++) {
                    BhR[nt][kc][0] = Wh2[col * W_PAD + kc * 8 + tq];
                    BhR[nt][kc][1] = Wh2[col * W_PAD + kc * 8 + tq + 4];
                }
            }
        }

        // wait for this tile's gather
        MBAR_WAIT(smb + 4 * OFF_MBAR + 8 * st, st ? ph1 : ph0);
        if (st) ph1 ^= 1; else ph0 ^= 1;
        __syncthreads();

        const uint32_t* Abuf = sm + (st ? OFF_A1 : OFF_A0);

        // ---- compute: 2 m-tiles x 4 n-tiles, 4 k-chunks (k=16), 2 terms ----
        float acc[2][4][4];
#pragma unroll
        for (int mt = 0; mt < 2; mt++)
#pragma unroll
            for (int nt = 0; nt < 4; nt++)
#pragma unroll
                for (int r = 0; r < 4; r++) acc[mt][nt][r] = 0.f;

#pragma unroll
        for (int kc = 0; kc < 4; kc++) {
            uint32_t ah[2][4], al[2][4];
#pragma unroll
            for (int mt = 0; mt < 2; mt++) {
                const uint32_t* p = Abuf + (EB + mt * 16 + gi) * A_STRIDE + kc * 8 + tq;
                ah[mt][0] = p[0];
                ah[mt][1] = p[8 * A_STRIDE];
                ah[mt][2] = p[4];
                ah[mt][3] = p[8 * A_STRIDE + 4];
                al[mt][0] = p[32];
                al[mt][1] = p[8 * A_STRIDE + 32];
                al[mt][2] = p[36];
                al[mt][3] = p[8 * A_STRIDE + 36];
            }
#pragma unroll
            for (int nt = 0; nt < 4; nt++) {
#pragma unroll
                for (int mt = 0; mt < 2; mt++) {
                    mma_f16(acc[mt][nt], ah[mt], BhR[nt][kc]);
                    mma_f16(acc[mt][nt], al[mt], BhR[nt][kc]);
                }
            }
        }

        // ---- scatter: thread owns logical couts NBASE+16p+4tq..+3 (v4) ----
        const int* oi = out_idx + (size_t)k * nE + ebase;
#pragma unroll
        for (int mt = 0; mt < 2; mt++) {
            const int r0 = EB + mt * 16 + gi;
            const int og0 = (ebase + r0 < nE) ? __ldg(oi + r0) : -1;
            const int og1 = (ebase + r0 + 8 < nE) ? __ldg(oi + r0 + 8) : -1;
#pragma unroll
            for (int p = 0; p < 2; p++) {
                const int cbase = NBASE + 16 * p + 4 * tq;
                if (og0 >= 0)
                    red_add_v4(yout + (size_t)og0 * 64 + cbase,
                               acc[mt][2 * p][0], acc[mt][2 * p][1],
                               acc[mt][2 * p + 1][0], acc[mt][2 * p + 1][1]);
                if (og1 >= 0)
                    red_add_v4(yout + (size_t)og1 * 64 + cbase,
                               acc[mt][2 * p][2], acc[mt][2 * p][3],
                               acc[mt][2 * p + 1][2], acc[mt][2 * p + 1][3]);
            }
        }
        __syncthreads();  // all reads of stage st done -> safe to re-issue into it
    }
}

// ---------------------------------------------------------------------------
// xc[row] = fp16 hi/lo split of (optionally BN+ReLU of) src row.
// thread j of row r handles channels (2j, 2j+1) -> hi word r*64+j, lo +32.
template <bool BN>
__global__ __launch_bounds__(256) void convert_kernel(const float2* __restrict__ src,
                                                      uint32_t* __restrict__ dst,
                                                      const float* __restrict__ bnp,
                                                      int n32) {
    int i = blockIdx.x * blockDim.x + threadIdx.x;
    if (i >= n32) return;
    int j = i & 31, row = i >> 5;
    float2 v = src[i];
    if (BN) {
        float2 sc = *(const float2*)(bnp + 2 * j);
        float2 sh = *(const float2*)(bnp + 64 + 2 * j);
        v.x = fmaxf(fmaf(v.x, sc.x, sh.x), 0.f);
        v.y = fmaxf(fmaf(v.y, sc.y, sh.y), 0.f);
    }
    uint32_t h, l;
    split_fp16(v, h, l);
    dst[(size_t)row * 64 + j] = h;
    dst[(size_t)row * 64 + 32 + j] = l;
}

// ---------------------------------------------------------------------------
__global__ __launch_bounds__(256) void stats_kernel(const float* __restrict__ y,
                                                    float2* __restrict__ sums, int n) {
    const int lane = threadIdx.x & 31;
    const int warp = threadIdx.x >> 5;
    const int wpb = blockDim.x >> 5;

    float2 s = {0.f, 0.f}, q = {0.f, 0.f};
    for (int r = blockIdx.x * wpb + warp; r < n; r += gridDim.x * wpb) {
        float2 v = *(const float2*)(y + (size_t)r * 64 + 2 * lane);
        s.x += v.x; s.y += v.y;
        q.x = fmaf(v.x, v.x, q.x);
        q.y = fmaf(v.y, v.y, q.y);
    }
    __shared__ float2 sh_s[8][32], sh_q[8][32];
    sh_s[warp][lane] = s;
    sh_q[warp][lane] = q;
    __syncthreads();
    if (warp == 0) {
        for (int i = 1; i < wpb; i++) {
            s.x += sh_s[i][lane].x; s.y += sh_s[i][lane].y;
            q.x += sh_q[i][lane].x; q.y += sh_q[i][lane].y;
        }
        atomicAdd(&sums[lane], s);
        atomicAdd(&sums[32 + lane], q);
    }
}

__global__ void finalize_kernel(const float2* __restrict__ sums,
                                const float* __restrict__ gamma,
                                const float* __restrict__ beta,
                                float* __restrict__ bnout, float invN) {
    int l = threadIdx.x;  // 0..31 -> channels 2l, 2l+1
    float2 s = sums[l], q = sums[32 + l];
    float m0 = s.x * invN, m1 = s.y * invN;
    float v0 = fmaf(q.x, invN, -m0 * m0);
    float v1 = fmaf(q.y, invN, -m1 * m1);
    float sc0 = gamma[2 * l] * rsqrtf(v0 + 1e-5f);
    float sc1 = gamma[2 * l + 1] * rsqrtf(v1 + 1e-5f);
    bnout[2 * l] = sc0;
    bnout[2 * l + 1] = sc1;
    bnout[64 + 2 * l] = beta[2 * l] - m0 * sc0;
    bnout[64 + 2 * l + 1] = beta[2 * l + 1] - m1 * sc1;
}

__global__ __launch_bounds__(256) void final_kernel(const float4* __restrict__ y2,
                                                    const float4* __restrict__ x,
                                                    const float* __restrict__ bn,
                                                    float4* __restrict__ out, int n4) {
    int i = blockIdx.x * blockDim.x + threadIdx.x;
    if (i >= n4) return;
    int c4 = (i & 15) * 4;
    float4 v = y2[i], xr = x[i];
    float4 sc = *(const float4*)(bn + c4);
    float4 sh = *(const float4*)(bn + 64 + c4);
    float4 o;
    o.x = fmaxf(fmaf(v.x, sc.x, sh.x) + xr.x, 0.f);
    o.y = fmaxf(fmaf(v.y, sc.y, sh.y) + xr.y, 0.f);
    o.z = fmaxf(fmaf(v.z, sc.z, sh.z) + xr.z, 0.f);
    o.w = fmaxf(fmaf(v.w, sc.w, sh.w) + xr.w, 0.f);
    out[i] = o;
}

// ---------------------------------------------------------------------------
extern "C" void kernel_launch(void* const* d_in, const int* in_sizes, int n_in,
                              void* d_out, int out_size) {
    const float* x      = (const float*)d_in[0];
    const float* W1     = (const float*)d_in[2];
    const float* gamma1 = (const float*)d_in[3];
    const float* beta1  = (const float*)d_in[4];
    const float* W2     = (const float*)d_in[5];
    const float* gamma2 = (const float*)d_in[6];
    const float* beta2  = (const float*)d_in[7];
    const int* in_idx   = (const int*)d_in[8];
    const int* out_idx  = (const int*)d_in[9];

    const int N = in_sizes[0] / 64;
    const int K = in_sizes[2] / (64 * 64);

    float *y1, *y2, *bn;
    uint32_t *xc, *y1c;
    float2* stats;
    cudaGetSymbolAddress((void**)&xc, g_xc);
    cudaGetSymbolAddress((void**)&y1c, g_y1c);
    cudaGetSymbolAddress((void**)&y1, g_y1);
    cudaGetSymbolAddress((void**)&y2, g_y2);
    cudaGetSymbolAddress((void**)&stats, g_stats);
    cudaGetSymbolAddress((void**)&bn, g_bn);

    cudaFuncSetAttribute(conv_mma_kernel,
                         cudaFuncAttributeMaxDynamicSharedMemorySize, SMEM_BYTES);

    cudaMemsetAsync(y1, 0, (size_t)N * 64 * sizeof(float));
    cudaMemsetAsync(y2, 0, (size_t)N * 64 * sizeof(float));
    cudaMemsetAsync(stats, 0, 4 * 32 * sizeof(float2));

    const int NB = 296;  // 2 CTAs per SM
    const float invN = 1.0f / (float)N;
    const int n32 = N * 32;

    // layer 1
    convert_kernel<false><<<(n32 + 255) / 256, 256>>>((const float2*)x, xc, nullptr, n32);
    conv_mma_kernel<<<NB, 256, SMEM_BYTES>>>(xc, W1, in_idx, out_idx, y1, N, K, NB);
    stats_kernel<<<256, 256>>>(y1, stats, N);
    finalize_kernel<<<1, 32>>>(stats, gamma1, beta1, bn, invN);

    // layer 2 (BN1 + ReLU folded into the split)
    convert_kernel<true><<<(n32 + 255) / 256, 256>>>((const float2*)y1, y1c, bn, n32);
    conv_mma_kernel<<<NB, 256, SMEM_BYTES>>>(y1c, W2, in_idx, out_idx, y2, N, K, NB);
    stats_kernel<<<256, 256>>>(y2, stats + 64, N);
    finalize_kernel<<<1, 32>>>(stats + 64, gamma2, beta2, bn + 128, invN);

    // epilogue: BN2 + residual + ReLU
    final_kernel<<<(N * 16 + 255) / 256, 256>>>((const float4*)y2, (const float4*)x,
                                                bn + 128, (float4*)d_out, N * 16);
}

// round 14
// speedup vs baseline: 1.8450x; 1.0765x over previous
#include <cuda_runtime.h>
#include <cuda_fp16.h>
#include <cstdint>

// ============================================================================
// ResidualBlockWithPointsBase — FP16 2-term mma.sync, warp-owns-full-cout
//   xc  = split_fp16(x);  y1 = conv(xc, W1); BN1 fold
//   y1c = split_fp16(relu(bn1(y1)));  y2 = conv(y1c, W2); BN2 fold
//   out = relu(bn2(y2) + x)
// conv: persistent CTAs over (k, 128-edge tile), double-buffered all-TMA
//   gather (256B/row = [hi 64fp16][lo 64fp16]). Warp owns 16 edges x ALL 64
//   couts (1 m-tile x 8 n-tiles) -> A fragments read exactly once.
//   W single fp16, 64 fragments register-resident per k. mma.m16n8k16
//   2-term (Ah*B + Al*B). red.global.add.v4.f32 scatter (column-permuted).
//   2 CTAs/SM.
// ============================================================================

#define MAXN 100352

__device__ uint32_t g_xc[MAXN * 64];   // [row][hi pairs 0..31 | lo pairs 32..63]
__device__ uint32_t g_y1c[MAXN * 64];
__device__ float g_y1[MAXN * 64];
__device__ float g_y2[MAXN * 64];
__device__ float2 g_stats[4 * 32];
__device__ float g_bn[4 * 64];

__device__ __forceinline__ void mma_f16(float* d, const uint32_t* a, const uint32_t* b) {
    asm volatile(
        "mma.sync.aligned.m16n8k16.row.col.f32.f16.f16.f32 "
        "{%0,%1,%2,%3}, {%4,%5,%6,%7}, {%8,%9}, {%0,%1,%2,%3};"
        : "+f"(d[0]), "+f"(d[1]), "+f"(d[2]), "+f"(d[3])
        : "r"(a[0]), "r"(a[1]), "r"(a[2]), "r"(a[3]), "r"(b[0]), "r"(b[1]));
}
__device__ __forceinline__ void red_add_v4(float* g, float a, float b, float c, float d) {
    asm volatile("red.global.add.v4.f32 [%0], {%1, %2, %3, %4};"
                 :: "l"(g), "f"(a), "f"(b), "f"(c), "f"(d) : "memory");
}
// split float2 into fp16x2 hi and lo words (x = h + l to ~2^-23)
__device__ __forceinline__ void split_fp16(float2 f, uint32_t& h, uint32_t& l) {
    __half2 hb = __floats2half2_rn(f.x, f.y);
    float hx = __half2float(__low2half(hb));
    float hy = __half2float(__high2half(hb));
    __half2 lb = __floats2half2_rn(f.x - hx, f.y - hy);
    h = *reinterpret_cast<uint32_t*>(&hb);
    l = *reinterpret_cast<uint32_t*>(&lb);
}

#define MBAR_WAIT(a, ph) do {                                                     \
    asm volatile("{\n\t.reg .pred P1;\n\tWL_%=:\n\t"                              \
        "mbarrier.try_wait.parity.acquire.cta.shared::cta.b64 P1, [%0], %1, 0x989680;\n\t" \
        "@P1 bra.uni WD_%=;\n\tbra.uni WL_%=;\n\tWD_%=:\n\t}"                     \
        :: "r"(a), "r"(ph) : "memory");                                           \
} while (0)

// smem layout (u32 units)
#define A_STRIDE 68                            // 272B/row (16B aligned)
#define OFF_A0 0
#define OFF_A1 (128 * A_STRIDE)                // 8704
#define OFF_WH (2 * 128 * A_STRIDE)            // 17408
#define W_PAD 36
#define OFF_MBAR (OFF_WH + 64 * W_PAD)         // 19712 (byte 78848, 8B aligned)
#define SMEM_U32 (OFF_MBAR + 4)
#define SMEM_BYTES (SMEM_U32 * 4)              // 78864

#define TILE_BYTES 32768u  // 128 rows x 256B payload

// ---------------------------------------------------------------------------
__global__ __launch_bounds__(256, 2) void conv_mma_kernel(
    const uint32_t* __restrict__ xc,  // [N][64] u32 (hi 0..31, lo 32..63)
    const float* __restrict__ W,      // [K][64][64]
    const int* __restrict__ in_idx, const int* __restrict__ out_idx,
    float* __restrict__ yout,         // [N][64] pre-zeroed
    int nE, int K, int nblk) {
    extern __shared__ uint32_t sm[];
    uint32_t* Wh2 = sm + OFF_WH;
    const uint32_t smb = (uint32_t)__cvta_generic_to_shared(sm);

    const int tid = threadIdx.x;
    const int lane = tid & 31;
    const int wid = tid >> 5;
    const int gi = lane >> 2;
    const int tq = lane & 3;
    const int EB = wid * 16;  // warp's edge base (16 edges, all 64 couts)

    const int tilesPerK = (nE + 127) >> 7;
    const int total = K * tilesPerK;
    const int chunk = (total + nblk - 1) / nblk;
    const int it0 = blockIdx.x * chunk;
    const int it1 = min(it0 + chunk, total);
    if (it0 >= it1) return;

    if (tid == 0) {
        asm volatile("mbarrier.init.shared.b64 [%0], 1;" :: "r"(smb + 4 * OFF_MBAR) : "memory");
        asm volatile("mbarrier.init.shared.b64 [%0], 1;" :: "r"(smb + 4 * OFF_MBAR + 8) : "memory");
        asm volatile("fence.proxy.async.shared::cta;" ::: "memory");
    }
    __syncthreads();

    auto load_idx = [&](int item) -> int {
        int k = item / tilesPerK;
        int e = (item - k * tilesPerK) * 128 + tid;
        return (e < nE) ? __ldg(in_idx + (size_t)k * nE + e) : 0;
    };
    auto issue = [&](int item, int src_row) {
        const uint32_t st = (uint32_t)(item & 1);
        const uint32_t mb = smb + 4 * OFF_MBAR + 8 * st;
        if (tid == 0)
            asm volatile("mbarrier.arrive.expect_tx.shared.b64 _, [%0], %1;"
                         :: "r"(mb), "r"(TILE_BYTES) : "memory");
        if (tid < 128) {
            const uint32_t* src = xc + (size_t)src_row * 64;
            uint32_t dst = smb + 4 * (st ? OFF_A1 : OFF_A0) + (uint32_t)tid * (A_STRIDE * 4);
            asm volatile(
                "cp.async.bulk.shared::cluster.global.mbarrier::complete_tx::bytes "
                "[%0], [%1], %2, [%3];"
                :: "r"(dst), "l"(src), "r"(256u), "r"(mb) : "memory");
        }
    };

    int cur_k = -1;
    uint32_t ph0 = 0, ph1 = 0;
    uint32_t BhR[8][4][2];  // W fp16 fragments, all 8 n-tiles, per k

    int nidx = (tid < 128) ? load_idx(it0) : 0;
    issue(it0, nidx);
    nidx = (tid < 128 && it0 + 1 < it1) ? load_idx(it0 + 1) : 0;

    for (int item = it0; item < it1; item++) {
        const int k = item / tilesPerK;
        const int tile = item - k * tilesPerK;
        const int ebase = tile * 128;
        const int st = item & 1;

        if (item + 1 < it1) {
            issue(item + 1, nidx);
            nidx = (tid < 128 && item + 2 < it1) ? load_idx(item + 2) : 0;
        }

        if (k != cur_k) {  // W restage (smem bounce) + load fragments into regs
            cur_k = k;
            const float* Wk = W + (size_t)k * 4096;
            for (int i = tid; i < 2048; i += 256) {
                int colP = i >> 5, j = i & 31;  // j = k-pair (k = 2j, 2j+1)
                int l16 = colP & 15;
                // inverse column permutation (for v4 scatter)
                int Lcol = (colP & ~15) + 4 * ((l16 >> 1) & 3) + 2 * ((l16 >> 3) & 1) + (l16 & 1);
                float w0 = __ldg(Wk + (size_t)(2 * j) * 64 + Lcol);
                float w1 = __ldg(Wk + (size_t)(2 * j + 1) * 64 + Lcol);
                __half2 w2 = __floats2half2_rn(w0, w1);
                Wh2[colP * W_PAD + j] = *reinterpret_cast<uint32_t*>(&w2);
            }
            __syncthreads();
#pragma unroll
            for (int nt = 0; nt < 8; nt++) {
                const int col = nt * 8 + gi;
#pragma unroll
                for (int kc = 0; kc < 4; kc++) {
                    BhR[nt][kc][0] = Wh2[col * W_PAD + kc * 8 + tq];
                    BhR[nt][kc][1] = Wh2[col * W_PAD + kc * 8 + tq + 4];
                }
            }
        }

        // wait for this tile's gather
        MBAR_WAIT(smb + 4 * OFF_MBAR + 8 * st, st ? ph1 : ph0);
        if (st) ph1 ^= 1; else ph0 ^= 1;
        __syncthreads();

        const uint32_t* Abuf = sm + (st ? OFF_A1 : OFF_A0);

        // ---- compute: 1 m-tile x 8 n-tiles, 4 k-chunks (k=16), 2 terms ----
        float acc[8][4];
#pragma unroll
        for (int nt = 0; nt < 8; nt++)
#pragma unroll
            for (int r = 0; r < 4; r++) acc[nt][r] = 0.f;

#pragma unroll
        for (int kc = 0; kc < 4; kc++) {
            uint32_t ah[4], al[4];
            {
                const uint32_t* p = Abuf + (EB + gi) * A_STRIDE + kc * 8 + tq;
                ah[0] = p[0];
                ah[1] = p[8 * A_STRIDE];
                ah[2] = p[4];
                ah[3] = p[8 * A_STRIDE + 4];
                al[0] = p[32];
                al[1] = p[8 * A_STRIDE + 32];
                al[2] = p[36];
                al[3] = p[8 * A_STRIDE + 36];
            }
#pragma unroll
            for (int nt = 0; nt < 8; nt++) {
                mma_f16(acc[nt], ah, BhR[nt][kc]);
                mma_f16(acc[nt], al, BhR[nt][kc]);
            }
        }

        // ---- scatter: per edge row, thread owns couts {16g+4tq..+3}, g=0..3 ----
        const int* oi = out_idx + (size_t)k * nE + ebase;
        {
            const int r0 = EB + gi;
            const int og0 = (ebase + r0 < nE) ? __ldg(oi + r0) : -1;
            const int og1 = (ebase + r0 + 8 < nE) ? __ldg(oi + r0 + 8) : -1;
#pragma unroll
            for (int g = 0; g < 4; g++) {
                const int cbase = 16 * g + 4 * tq;
                if (og0 >= 0)
                    red_add_v4(yout + (size_t)og0 * 64 + cbase,
                               acc[2 * g][0], acc[2 * g][1],
                               acc[2 * g + 1][0], acc[2 * g + 1][1]);
                if (og1 >= 0)
                    red_add_v4(yout + (size_t)og1 * 64 + cbase,
                               acc[2 * g][2], acc[2 * g][3],
                               acc[2 * g + 1][2], acc[2 * g + 1][3]);
            }
        }
        __syncthreads();  // all reads of stage st done -> safe to re-issue into it
    }
}

// ---------------------------------------------------------------------------
// xc[row] = fp16 hi/lo split of (optionally BN+ReLU of) src row.
template <bool BN>
__global__ __launch_bounds__(256) void convert_kernel(const float2* __restrict__ src,
                                                      uint32_t* __restrict__ dst,
                                                      const float* __restrict__ bnp,
                                                      int n32) {
    int i = blockIdx.x * blockDim.x + threadIdx.x;
    if (i >= n32) return;
    int j = i & 31, row = i >> 5;
    float2 v = src[i];
    if (BN) {
        float2 sc = *(const float2*)(bnp + 2 * j);
        float2 sh = *(const float2*)(bnp + 64 + 2 * j);
        v.x = fmaxf(fmaf(v.x, sc.x, sh.x), 0.f);
        v.y = fmaxf(fmaf(v.y, sc.y, sh.y), 0.f);
    }
    uint32_t h, l;
    split_fp16(v, h, l);
    dst[(size_t)row * 64 + j] = h;
    dst[(size_t)row * 64 + 32 + j] = l;
}

// ---------------------------------------------------------------------------
__global__ __launch_bounds__(256) void stats_kernel(const float* __restrict__ y,
                                                    float2* __restrict__ sums, int n) {
    const int lane = threadIdx.x & 31;
    const int warp = threadIdx.x >> 5;
    const int wpb = blockDim.x >> 5;

    float2 s = {0.f, 0.f}, q = {0.f, 0.f};
    for (int r = blockIdx.x * wpb + warp; r < n; r += gridDim.x * wpb) {
        float2 v = *(const float2*)(y + (size_t)r * 64 + 2 * lane);
        s.x += v.x; s.y += v.y;
        q.x = fmaf(v.x, v.x, q.x);
        q.y = fmaf(v.y, v.y, q.y);
    }
    __shared__ float2 sh_s[8][32], sh_q[8][32];
    sh_s[warp][lane] = s;
    sh_q[warp][lane] = q;
    __syncthreads();
    if (warp == 0) {
        for (int i = 1; i < wpb; i++) {
            s.x += sh_s[i][lane].x; s.y += sh_s[i][lane].y;
            q.x += sh_q[i][lane].x; q.y += sh_q[i][lane].y;
        }
        atomicAdd(&sums[lane], s);
        atomicAdd(&sums[32 + lane], q);
    }
}

__global__ void finalize_kernel(const float2* __restrict__ sums,
                                const float* __restrict__ gamma,
                                const float* __restrict__ beta,
                                float* __restrict__ bnout, float invN) {
    int l = threadIdx.x;  // 0..31 -> channels 2l, 2l+1
    float2 s = sums[l], q = sums[32 + l];
    float m0 = s.x * invN, m1 = s.y * invN;
    float v0 = fmaf(q.x, invN, -m0 * m0);
    float v1 = fmaf(q.y, invN, -m1 * m1);
    float sc0 = gamma[2 * l] * rsqrtf(v0 + 1e-5f);
    float sc1 = gamma[2 * l + 1] * rsqrtf(v1 + 1e-5f);
    bnout[2 * l] = sc0;
    bnout[2 * l + 1] = sc1;
    bnout[64 + 2 * l] = beta[2 * l] - m0 * sc0;
    bnout[64 + 2 * l + 1] = beta[2 * l + 1] - m1 * sc1;
}

__global__ __launch_bounds__(256) void final_kernel(const float4* __restrict__ y2,
                                                    const float4* __restrict__ x,
                                                    const float* __restrict__ bn,
                                                    float4* __restrict__ out, int n4) {
    int i = blockIdx.x * blockDim.x + threadIdx.x;
    if (i >= n4) return;
    int c4 = (i & 15) * 4;
    float4 v = y2[i], xr = x[i];
    float4 sc = *(const float4*)(bn + c4);
    float4 sh = *(const float4*)(bn + 64 + c4);
    float4 o;
    o.x = fmaxf(fmaf(v.x, sc.x, sh.x) + xr.x, 0.f);
    o.y = fmaxf(fmaf(v.y, sc.y, sh.y) + xr.y, 0.f);
    o.z = fmaxf(fmaf(v.z, sc.z, sh.z) + xr.z, 0.f);
    o.w = fmaxf(fmaf(v.w, sc.w, sh.w) + xr.w, 0.f);
    out[i] = o;
}

// ---------------------------------------------------------------------------
extern "C" void kernel_launch(void* const* d_in, const int* in_sizes, int n_in,
                              void* d_out, int out_size) {
    const float* x      = (const float*)d_in[0];
    const float* W1     = (const float*)d_in[2];
    const float* gamma1 = (const float*)d_in[3];
    const float* beta1  = (const float*)d_in[4];
    const float* W2     = (const float*)d_in[5];
    const float* gamma2 = (const float*)d_in[6];
    const float* beta2  = (const float*)d_in[7];
    const int* in_idx   = (const int*)d_in[8];
    const int* out_idx  = (const int*)d_in[9];

    const int N = in_sizes[0] / 64;
    const int K = in_sizes[2] / (64 * 64);

    float *y1, *y2, *bn;
    uint32_t *xc, *y1c;
    float2* stats;
    cudaGetSymbolAddress((void**)&xc, g_xc);
    cudaGetSymbolAddress((void**)&y1c, g_y1c);
    cudaGetSymbolAddress((void**)&y1, g_y1);
    cudaGetSymbolAddress((void**)&y2, g_y2);
    cudaGetSymbolAddress((void**)&stats, g_stats);
    cudaGetSymbolAddress((void**)&bn, g_bn);

    cudaFuncSetAttribute(conv_mma_kernel,
                         cudaFuncAttributeMaxDynamicSharedMemorySize, SMEM_BYTES);

    cudaMemsetAsync(y1, 0, (size_t)N * 64 * sizeof(float));
    cudaMemsetAsync(y2, 0, (size_t)N * 64 * sizeof(float));
    cudaMemsetAsync(stats, 0, 4 * 32 * sizeof(float2));

    const int NB = 296;  // 2 CTAs per SM
    const float invN = 1.0f / (float)N;
    const int n32 = N * 32;

    // layer 1
    convert_kernel<false><<<(n32 + 255) / 256, 256>>>((const float2*)x, xc, nullptr, n32);
    conv_mma_kernel<<<NB, 256, SMEM_BYTES>>>(xc, W1, in_idx, out_idx, y1, N, K, NB);
    stats_kernel<<<256, 256>>>(y1, stats, N);
    finalize_kernel<<<1, 32>>>(stats, gamma1, beta1, bn, invN);

    // layer 2 (BN1 + ReLU folded into the split)
    convert_kernel<true><<<(n32 + 255) / 256, 256>>>((const float2*)y1, y1c, bn, n32);
    conv_mma_kernel<<<NB, 256, SMEM_BYTES>>>(y1c, W2, in_idx, out_idx, y2, N, K, NB);
    stats_kernel<<<256, 256>>>(y2, stats + 64, N);
    finalize_kernel<<<1, 32>>>(stats + 64, gamma2, beta2, bn + 128, invN);

    // epilogue: BN2 + residual + ReLU
    final_kernel<<<(N * 16 + 255) / 256, 256>>>((const float4*)y2, (const float4*)x,
                                                bn + 128, (float4*)d_out, N * 16);
}

// round 15
// speedup vs baseline: 1.9724x; 1.0690x over previous
#include <cuda_runtime.h>
#include <cuda_fp16.h>
#include <cstdint>

// ============================================================================
// ResidualBlockWithPointsBase — FP16 2-term mma.sync, 3-stage TMA pipeline
//   xc  = split_fp16(x);  y1 = conv(xc, W1); BN1 fold
//   y1c = split_fp16(relu(bn1(y1)));  y2 = conv(y1c, W2); BN2 fold
//   out = relu(bn2(y2) + x)
// conv: persistent CTAs over (k, 128-edge tile), 3-stage all-TMA gather
//   (256B/row = [hi 64fp16][lo 64fp16]), prefetch distance 2, ONE
//   __syncthreads per tile (post-wait barrier covers WAR on stage reuse).
//   Warp owns 16 edges x all 64 couts; W fp16 fragments register-resident.
//   mma.m16n8k16 2-term (Ah*B + Al*B). red.global.add.v4.f32 scatter
//   (column-permuted). 2 CTAs/SM.
// ============================================================================

#define MAXN 100352

__device__ uint32_t g_xc[MAXN * 64];   // [row][hi pairs 0..31 | lo pairs 32..63]
__device__ uint32_t g_y1c[MAXN * 64];
__device__ float g_y1[MAXN * 64];
__device__ float g_y2[MAXN * 64];
__device__ float2 g_stats[4 * 32];
__device__ float g_bn[4 * 64];

__device__ __forceinline__ void mma_f16(float* d, const uint32_t* a, const uint32_t* b) {
    asm volatile(
        "mma.sync.aligned.m16n8k16.row.col.f32.f16.f16.f32 "
        "{%0,%1,%2,%3}, {%4,%5,%6,%7}, {%8,%9}, {%0,%1,%2,%3};"
        : "+f"(d[0]), "+f"(d[1]), "+f"(d[2]), "+f"(d[3])
        : "r"(a[0]), "r"(a[1]), "r"(a[2]), "r"(a[3]), "r"(b[0]), "r"(b[1]));
}
__device__ __forceinline__ void red_add_v4(float* g, float a, float b, float c, float d) {
    asm volatile("red.global.add.v4.f32 [%0], {%1, %2, %3, %4};"
                 :: "l"(g), "f"(a), "f"(b), "f"(c), "f"(d) : "memory");
}
// split float2 into fp16x2 hi and lo words (x = h + l to ~2^-23)
__device__ __forceinline__ void split_fp16(float2 f, uint32_t& h, uint32_t& l) {
    __half2 hb = __floats2half2_rn(f.x, f.y);
    float hx = __half2float(__low2half(hb));
    float hy = __half2float(__high2half(hb));
    __half2 lb = __floats2half2_rn(f.x - hx, f.y - hy);
    h = *reinterpret_cast<uint32_t*>(&hb);
    l = *reinterpret_cast<uint32_t*>(&lb);
}

#define MBAR_WAIT(a, ph) do {                                                     \
    asm volatile("{\n\t.reg .pred P1;\n\tWL_%=:\n\t"                              \
        "mbarrier.try_wait.parity.acquire.cta.shared::cta.b64 P1, [%0], %1, 0x989680;\n\t" \
        "@P1 bra.uni WD_%=;\n\tbra.uni WL_%=;\n\tWD_%=:\n\t}"                     \
        :: "r"(a), "r"(ph) : "memory");                                           \
} while (0)

// smem layout (u32 units)
#define A_STRIDE 68                            // 272B/row (16B aligned)
#define STAGE_U32 (128 * A_STRIDE)             // 8704 u32 per stage
#define NSTAGE 3
#define OFF_WH (NSTAGE * STAGE_U32)            // 26112
#define W_PAD 36
#define OFF_MBAR (OFF_WH + 64 * W_PAD)         // 28416 (byte 113664, 8B aligned)
#define SMEM_U32 (OFF_MBAR + 2 * NSTAGE)
#define SMEM_BYTES (SMEM_U32 * 4)              // 113688

#define TILE_BYTES 32768u  // 128 rows x 256B payload

// ---------------------------------------------------------------------------
__global__ __launch_bounds__(256, 2) void conv_mma_kernel(
    const uint32_t* __restrict__ xc,  // [N][64] u32 (hi 0..31, lo 32..63)
    const float* __restrict__ W,      // [K][64][64]
    const int* __restrict__ in_idx, const int* __restrict__ out_idx,
    float* __restrict__ yout,         // [N][64] pre-zeroed
    int nE, int K, int nblk) {
    extern __shared__ uint32_t sm[];
    uint32_t* Wh2 = sm + OFF_WH;
    const uint32_t smb = (uint32_t)__cvta_generic_to_shared(sm);

    const int tid = threadIdx.x;
    const int lane = tid & 31;
    const int wid = tid >> 5;
    const int gi = lane >> 2;
    const int tq = lane & 3;
    const int EB = wid * 16;  // warp's edge base (16 edges, all 64 couts)

    const int tilesPerK = (nE + 127) >> 7;
    const int total = K * tilesPerK;
    const int chunk = (total + nblk - 1) / nblk;
    const int it0 = blockIdx.x * chunk;
    const int it1 = min(it0 + chunk, total);
    if (it0 >= it1) return;

    if (tid == 0) {
#pragma unroll
        for (int s = 0; s < NSTAGE; s++)
            asm volatile("mbarrier.init.shared.b64 [%0], 1;"
                         :: "r"(smb + 4 * OFF_MBAR + 8 * s) : "memory");
        asm volatile("fence.proxy.async.shared::cta;" ::: "memory");
    }
    __syncthreads();

    auto load_idx = [&](int item) -> int {
        int k = item / tilesPerK;
        int e = (item - k * tilesPerK) * 128 + tid;
        return (e < nE) ? __ldg(in_idx + (size_t)k * nE + e) : 0;
    };
    auto issue = [&](int item, int src_row) {
        const uint32_t st = (uint32_t)((item - it0) % NSTAGE);
        const uint32_t mb = smb + 4 * OFF_MBAR + 8 * st;
        if (tid == 0)
            asm volatile("mbarrier.arrive.expect_tx.shared.b64 _, [%0], %1;"
                         :: "r"(mb), "r"(TILE_BYTES) : "memory");
        if (tid < 128) {
            const uint32_t* src = xc + (size_t)src_row * 64;
            uint32_t dst = smb + 4 * st * STAGE_U32 + (uint32_t)tid * (A_STRIDE * 4);
            asm volatile(
                "cp.async.bulk.shared::cluster.global.mbarrier::complete_tx::bytes "
                "[%0], [%1], %2, [%3];"
                :: "r"(dst), "l"(src), "r"(256u), "r"(mb) : "memory");
        }
    };

    int cur_k = -1;
    uint32_t BhR[8][4][2];  // W fp16 fragments, all 8 n-tiles, per k

    // prologue: two tiles in flight
    int nidx = (tid < 128) ? load_idx(it0) : 0;
    issue(it0, nidx);
    if (it0 + 1 < it1) {
        nidx = (tid < 128) ? load_idx(it0 + 1) : 0;
        issue(it0 + 1, nidx);
    }
    nidx = (tid < 128 && it0 + 2 < it1) ? load_idx(it0 + 2) : 0;

    for (int item = it0; item < it1; item++) {
        const int k = item / tilesPerK;
        const int tile = item - k * tilesPerK;
        const int ebase = tile * 128;
        const int rel = item - it0;
        const int st = rel % NSTAGE;

        // wait for this tile's gather; the following barrier also makes prior
        // readers of stage (rel+2)%NSTAGE done -> safe to re-issue into it.
        MBAR_WAIT(smb + 4 * OFF_MBAR + 8 * st, (rel / NSTAGE) & 1);
        __syncthreads();

        if (item + 2 < it1) {
            issue(item + 2, nidx);
            nidx = (tid < 128 && item + 3 < it1) ? load_idx(item + 3) : 0;
        }

        if (k != cur_k) {  // W restage (smem bounce) + load fragments into regs
            cur_k = k;
            const float* Wk = W + (size_t)k * 4096;
            for (int i = tid; i < 2048; i += 256) {
                int colP = i >> 5, j = i & 31;  // j = k-pair (k = 2j, 2j+1)
                int l16 = colP & 15;
                // inverse column permutation (for v4 scatter)
                int Lcol = (colP & ~15) + 4 * ((l16 >> 1) & 3) + 2 * ((l16 >> 3) & 1) + (l16 & 1);
                float w0 = __ldg(Wk + (size_t)(2 * j) * 64 + Lcol);
                float w1 = __ldg(Wk + (size_t)(2 * j + 1) * 64 + Lcol);
                __half2 w2 = __floats2half2_rn(w0, w1);
                Wh2[colP * W_PAD + j] = *reinterpret_cast<uint32_t*>(&w2);
            }
            __syncthreads();
#pragma unroll
            for (int nt = 0; nt < 8; nt++) {
                const int col = nt * 8 + gi;
#pragma unroll
                for (int kc = 0; kc < 4; kc++) {
                    BhR[nt][kc][0] = Wh2[col * W_PAD + kc * 8 + tq];
                    BhR[nt][kc][1] = Wh2[col * W_PAD + kc * 8 + tq + 4];
                }
            }
        }

        const uint32_t* Abuf = sm + st * STAGE_U32;

        // ---- compute: 1 m-tile x 8 n-tiles, 4 k-chunks (k=16), 2 terms ----
        float acc[8][4];
#pragma unroll
        for (int nt = 0; nt < 8; nt++)
#pragma unroll
            for (int r = 0; r < 4; r++) acc[nt][r] = 0.f;

#pragma unroll
        for (int kc = 0; kc < 4; kc++) {
            uint32_t ah[4], al[4];
            {
                const uint32_t* p = Abuf + (EB + gi) * A_STRIDE + kc * 8 + tq;
                ah[0] = p[0];
                ah[1] = p[8 * A_STRIDE];
                ah[2] = p[4];
                ah[3] = p[8 * A_STRIDE + 4];
                al[0] = p[32];
                al[1] = p[8 * A_STRIDE + 32];
                al[2] = p[36];
                al[3] = p[8 * A_STRIDE + 36];
            }
#pragma unroll
            for (int nt = 0; nt < 8; nt++) {
                mma_f16(acc[nt], ah, BhR[nt][kc]);
                mma_f16(acc[nt], al, BhR[nt][kc]);
            }
        }

        // ---- scatter: per edge row, thread owns couts {16g+4tq..+3}, g=0..3 ----
        const int* oi = out_idx + (size_t)k * nE + ebase;
        {
            const int r0 = EB + gi;
            const int og0 = (ebase + r0 < nE) ? __ldg(oi + r0) : -1;
            const int og1 = (ebase + r0 + 8 < nE) ? __ldg(oi + r0 + 8) : -1;
#pragma unroll
            for (int g = 0; g < 4; g++) {
                const int cbase = 16 * g + 4 * tq;
                if (og0 >= 0)
                    red_add_v4(yout + (size_t)og0 * 64 + cbase,
                               acc[2 * g][0], acc[2 * g][1],
                               acc[2 * g + 1][0], acc[2 * g + 1][1]);
                if (og1 >= 0)
                    red_add_v4(yout + (size_t)og1 * 64 + cbase,
                               acc[2 * g][2], acc[2 * g][3],
                               acc[2 * g + 1][2], acc[2 * g + 1][3]);
            }
        }
        // no trailing barrier: next iteration's post-wait __syncthreads covers
        // WAR before any re-issue into a stage (3-stage rotation).
    }
}

// ---------------------------------------------------------------------------
// xc[row] = fp16 hi/lo split of (optionally BN+ReLU of) src row.
template <bool BN>
__global__ __launch_bounds__(256) void convert_kernel(const float2* __restrict__ src,
                                                      uint32_t* __restrict__ dst,
                                                      const float* __restrict__ bnp,
                                                      int n32) {
    int i = blockIdx.x * blockDim.x + threadIdx.x;
    if (i >= n32) return;
    int j = i & 31, row = i >> 5;
    float2 v = src[i];
    if (BN) {
        float2 sc = *(const float2*)(bnp + 2 * j);
        float2 sh = *(const float2*)(bnp + 64 + 2 * j);
        v.x = fmaxf(fmaf(v.x, sc.x, sh.x), 0.f);
        v.y = fmaxf(fmaf(v.y, sc.y, sh.y), 0.f);
    }
    uint32_t h, l;
    split_fp16(v, h, l);
    dst[(size_t)row * 64 + j] = h;
    dst[(size_t)row * 64 + 32 + j] = l;
}

// ---------------------------------------------------------------------------
__global__ __launch_bounds__(256) void stats_kernel(const float* __restrict__ y,
                                                    float2* __restrict__ sums, int n) {
    const int lane = threadIdx.x & 31;
    const int warp = threadIdx.x >> 5;
    const int wpb = blockDim.x >> 5;

    float2 s = {0.f, 0.f}, q = {0.f, 0.f};
    for (int r = blockIdx.x * wpb + warp; r < n; r += gridDim.x * wpb) {
        float2 v = *(const float2*)(y + (size_t)r * 64 + 2 * lane);
        s.x += v.x; s.y += v.y;
        q.x = fmaf(v.x, v.x, q.x);
        q.y = fmaf(v.y, v.y, q.y);
    }
    __shared__ float2 sh_s[8][32], sh_q[8][32];
    sh_s[warp][lane] = s;
    sh_q[warp][lane] = q;
    __syncthreads();
    if (warp == 0) {
        for (int i = 1; i < wpb; i++) {
            s.x += sh_s[i][lane].x; s.y += sh_s[i][lane].y;
            q.x += sh_q[i][lane].x; q.y += sh_q[i][lane].y;
        }
        atomicAdd(&sums[lane], s);
        atomicAdd(&sums[32 + lane], q);
    }
}

__global__ void finalize_kernel(const float2* __restrict__ sums,
                                const float* __restrict__ gamma,
                                const float* __restrict__ beta,
                                float* __restrict__ bnout, float invN) {
    int l = threadIdx.x;  // 0..31 -> channels 2l, 2l+1
    float2 s = sums[l], q = sums[32 + l];
    float m0 = s.x * invN, m1 = s.y * invN;
    float v0 = fmaf(q.x, invN, -m0 * m0);
    float v1 = fmaf(q.y, invN, -m1 * m1);
    float sc0 = gamma[2 * l] * rsqrtf(v0 + 1e-5f);
    float sc1 = gamma[2 * l + 1] * rsqrtf(v1 + 1e-5f);
    bnout[2 * l] = sc0;
    bnout[2 * l + 1] = sc1;
    bnout[64 + 2 * l] = beta[2 * l] - m0 * sc0;
    bnout[64 + 2 * l + 1] = beta[2 * l + 1] - m1 * sc1;
}

__global__ __launch_bounds__(256) void final_kernel(const float4* __restrict__ y2,
                                                    const float4* __restrict__ x,
                                                    const float* __restrict__ bn,
                                                    float4* __restrict__ out, int n4) {
    int i = blockIdx.x * blockDim.x + threadIdx.x;
    if (i >= n4) return;
    int c4 = (i & 15) * 4;
    float4 v = y2[i], xr = x[i];
    float4 sc = *(const float4*)(bn + c4);
    float4 sh = *(const float4*)(bn + 64 + c4);
    float4 o;
    o.x = fmaxf(fmaf(v.x, sc.x, sh.x) + xr.x, 0.f);
    o.y = fmaxf(fmaf(v.y, sc.y, sh.y) + xr.y, 0.f);
    o.z = fmaxf(fmaf(v.z, sc.z, sh.z) + xr.z, 0.f);
    o.w = fmaxf(fmaf(v.w, sc.w, sh.w) + xr.w, 0.f);
    out[i] = o;
}

// ---------------------------------------------------------------------------
extern "C" void kernel_launch(void* const* d_in, const int* in_sizes, int n_in,
                              void* d_out, int out_size) {
    const float* x      = (const float*)d_in[0];
    const float* W1     = (const float*)d_in[2];
    const float* gamma1 = (const float*)d_in[3];
    const float* beta1  = (const float*)d_in[4];
    const float* W2     = (const float*)d_in[5];
    const float* gamma2 = (const float*)d_in[6];
    const float* beta2  = (const float*)d_in[7];
    const int* in_idx   = (const int*)d_in[8];
    const int* out_idx  = (const int*)d_in[9];

    const int N = in_sizes[0] / 64;
    const int K = in_sizes[2] / (64 * 64);

    float *y1, *y2, *bn;
    uint32_t *xc, *y1c;
    float2* stats;
    cudaGetSymbolAddress((void**)&xc, g_xc);
    cudaGetSymbolAddress((void**)&y1c, g_y1c);
    cudaGetSymbolAddress((void**)&y1, g_y1);
    cudaGetSymbolAddress((void**)&y2, g_y2);
    cudaGetSymbolAddress((void**)&stats, g_stats);
    cudaGetSymbolAddress((void**)&bn, g_bn);

    cudaFuncSetAttribute(conv_mma_kernel,
                         cudaFuncAttributeMaxDynamicSharedMemorySize, SMEM_BYTES);

    cudaMemsetAsync(y1, 0, (size_t)N * 64 * sizeof(float));
    cudaMemsetAsync(y2, 0, (size_t)N * 64 * sizeof(float));
    cudaMemsetAsync(stats, 0, 4 * 32 * sizeof(float2));

    const int NB = 296;  // 2 CTAs per SM
    const float invN = 1.0f / (float)N;
    const int n32 = N * 32;

    // layer 1
    convert_kernel<false><<<(n32 + 255) / 256, 256>>>((const float2*)x, xc, nullptr, n32);
    conv_mma_kernel<<<NB, 256, SMEM_BYTES>>>(xc, W1, in_idx, out_idx, y1, N, K, NB);
    stats_kernel<<<256, 256>>>(y1, stats, N);
    finalize_kernel<<<1, 32>>>(stats, gamma1, beta1, bn, invN);

    // layer 2 (BN1 + ReLU folded into the split)
    convert_kernel<true><<<(n32 + 255) / 256, 256>>>((const float2*)y1, y1c, bn, n32);
    conv_mma_kernel<<<NB, 256, SMEM_BYTES>>>(y1c, W2, in_idx, out_idx, y2, N, K, NB);
    stats_kernel<<<256, 256>>>(y2, stats + 64, N);
    finalize_kernel<<<1, 32>>>(stats + 64, gamma2, beta2, bn + 128, invN);

    // epilogue: BN2 + residual + ReLU
    final_kernel<<<(N * 16 + 255) / 256, 256>>>((const float4*)y2, (const float4*)x,
                                                bn + 128, (float4*)d_out, N * 16);
}

// round 16
// speedup vs baseline: 2.1430x; 1.0865x over previous
#include <cuda_runtime.h>
#include <cuda_fp16.h>
#include <cstdint>

// ============================================================================
// ResidualBlockWithPointsBase — FP16 1-term mma.sync, 4-stage TMA pipeline
//   xc  = fp16(x);  y1 = conv(xc, W1); BN1 fold
//   y1c = fp16(relu(bn1(y1)));  y2 = conv(y1c, W2); BN2 fold
//   out = relu(bn2(y2) + x)
// conv: persistent CTAs over (k, 128-edge tile), 4-stage all-TMA gather
//   (128B/row fp16), prefetch distance 3, ONE __syncthreads per tile.
//   Warp owns 16 edges x all 64 couts; W fp16 fragments register-resident.
//   Single-term mma.m16n8k16 (A*B). red.global.add.v4.f32 scatter
//   (column-permuted). 2 CTAs/SM.
// Precision: W fp16 (~2.1e-4, measured) + x fp16 (~2.1e-4) -> ~3-4.5e-4 total,
// inside the 1e-3 tolerance with >2x margin.
// ============================================================================

#define MAXN 100352

__device__ uint32_t g_xc[MAXN * 32];   // [row][fp16x2 pairs 0..31]
__device__ uint32_t g_y1c[MAXN * 32];
__device__ float g_y1[MAXN * 64];
__device__ float g_y2[MAXN * 64];
__device__ float2 g_stats[4 * 32];
__device__ float g_bn[4 * 64];

__device__ __forceinline__ void mma_f16(float* d, const uint32_t* a, const uint32_t* b) {
    asm volatile(
        "mma.sync.aligned.m16n8k16.row.col.f32.f16.f16.f32 "
        "{%0,%1,%2,%3}, {%4,%5,%6,%7}, {%8,%9}, {%0,%1,%2,%3};"
        : "+f"(d[0]), "+f"(d[1]), "+f"(d[2]), "+f"(d[3])
        : "r"(a[0]), "r"(a[1]), "r"(a[2]), "r"(a[3]), "r"(b[0]), "r"(b[1]));
}
__device__ __forceinline__ void red_add_v4(float* g, float a, float b, float c, float d) {
    asm volatile("red.global.add.v4.f32 [%0], {%1, %2, %3, %4};"
                 :: "l"(g), "f"(a), "f"(b), "f"(c), "f"(d) : "memory");
}

#define MBAR_WAIT(a, ph) do {                                                     \
    asm volatile("{\n\t.reg .pred P1;\n\tWL_%=:\n\t"                              \
        "mbarrier.try_wait.parity.acquire.cta.shared::cta.b64 P1, [%0], %1, 0x989680;\n\t" \
        "@P1 bra.uni WD_%=;\n\tbra.uni WL_%=;\n\tWD_%=:\n\t}"                     \
        :: "r"(a), "r"(ph) : "memory");                                           \
} while (0)

// smem layout (u32 units)
#define A_STRIDE 36                            // 144B/row (16B aligned), 128B payload
#define STAGE_U32 (128 * A_STRIDE)             // 4608 u32 per stage
#define NSTAGE 4
#define OFF_WH (NSTAGE * STAGE_U32)            // 18432
#define W_PAD 36
#define OFF_MBAR (OFF_WH + 64 * W_PAD)         // 20736 (byte 82944, 8B aligned)
#define SMEM_U32 (OFF_MBAR + 2 * NSTAGE)
#define SMEM_BYTES (SMEM_U32 * 4)              // 82976

#define TILE_BYTES 16384u  // 128 rows x 128B payload
#define PFD 3              // prefetch distance

// ---------------------------------------------------------------------------
__global__ __launch_bounds__(256, 2) void conv_mma_kernel(
    const uint32_t* __restrict__ xc,  // [N][32] u32 fp16x2 pairs
    const float* __restrict__ W,      // [K][64][64]
    const int* __restrict__ in_idx, const int* __restrict__ out_idx,
    float* __restrict__ yout,         // [N][64] pre-zeroed
    int nE, int K, int nblk) {
    extern __shared__ uint32_t sm[];
    uint32_t* Wh2 = sm + OFF_WH;
    const uint32_t smb = (uint32_t)__cvta_generic_to_shared(sm);

    const int tid = threadIdx.x;
    const int lane = tid & 31;
    const int wid = tid >> 5;
    const int gi = lane >> 2;
    const int tq = lane & 3;
    const int EB = wid * 16;  // warp's edge base (16 edges, all 64 couts)

    const int tilesPerK = (nE + 127) >> 7;
    const int total = K * tilesPerK;
    const int chunk = (total + nblk - 1) / nblk;
    const int it0 = blockIdx.x * chunk;
    const int it1 = min(it0 + chunk, total);
    if (it0 >= it1) return;

    if (tid == 0) {
#pragma unroll
        for (int s = 0; s < NSTAGE; s++)
            asm volatile("mbarrier.init.shared.b64 [%0], 1;"
                         :: "r"(smb + 4 * OFF_MBAR + 8 * s) : "memory");
        asm volatile("fence.proxy.async.shared::cta;" ::: "memory");
    }
    __syncthreads();

    auto load_idx = [&](int item) -> int {
        int k = item / tilesPerK;
        int e = (item - k * tilesPerK) * 128 + tid;
        return (e < nE) ? __ldg(in_idx + (size_t)k * nE + e) : 0;
    };
    auto issue = [&](int item, int src_row) {
        const uint32_t st = (uint32_t)((item - it0) % NSTAGE);
        const uint32_t mb = smb + 4 * OFF_MBAR + 8 * st;
        if (tid == 0)
            asm volatile("mbarrier.arrive.expect_tx.shared.b64 _, [%0], %1;"
                         :: "r"(mb), "r"(TILE_BYTES) : "memory");
        if (tid < 128) {
            const uint32_t* src = xc + (size_t)src_row * 32;
            uint32_t dst = smb + 4 * st * STAGE_U32 + (uint32_t)tid * (A_STRIDE * 4);
            asm volatile(
                "cp.async.bulk.shared::cluster.global.mbarrier::complete_tx::bytes "
                "[%0], [%1], %2, [%3];"
                :: "r"(dst), "l"(src), "r"(128u), "r"(mb) : "memory");
        }
    };

    int cur_k = -1;
    uint32_t BhR[8][4][2];  // W fp16 fragments, all 8 n-tiles, per k

    // prologue: PFD tiles in flight
    int nidx;
#pragma unroll
    for (int d = 0; d < PFD; d++) {
        if (it0 + d < it1) {
            nidx = (tid < 128) ? load_idx(it0 + d) : 0;
            issue(it0 + d, nidx);
        }
    }
    nidx = (tid < 128 && it0 + PFD < it1) ? load_idx(it0 + PFD) : 0;

    for (int item = it0; item < it1; item++) {
        const int k = item / tilesPerK;
        const int tile = item - k * tilesPerK;
        const int ebase = tile * 128;
        const int rel = item - it0;
        const int st = rel % NSTAGE;

        // wait for this tile's gather; barrier also finishes prior readers of
        // the stage we're about to re-issue into ((rel+PFD)%NSTAGE).
        MBAR_WAIT(smb + 4 * OFF_MBAR + 8 * st, (rel / NSTAGE) & 1);
        __syncthreads();

        if (item + PFD < it1) {
            issue(item + PFD, nidx);
            nidx = (tid < 128 && item + PFD + 1 < it1) ? load_idx(item + PFD + 1) : 0;
        }

        if (k != cur_k) {  // W restage (smem bounce) + load fragments into regs
            cur_k = k;
            const float* Wk = W + (size_t)k * 4096;
            for (int i = tid; i < 2048; i += 256) {
                int colP = i >> 5, j = i & 31;  // j = k-pair (k = 2j, 2j+1)
                int l16 = colP & 15;
                // inverse column permutation (for v4 scatter)
                int Lcol = (colP & ~15) + 4 * ((l16 >> 1) & 3) + 2 * ((l16 >> 3) & 1) + (l16 & 1);
                float w0 = __ldg(Wk + (size_t)(2 * j) * 64 + Lcol);
                float w1 = __ldg(Wk + (size_t)(2 * j + 1) * 64 + Lcol);
                __half2 w2 = __floats2half2_rn(w0, w1);
                Wh2[colP * W_PAD + j] = *reinterpret_cast<uint32_t*>(&w2);
            }
            __syncthreads();
#pragma unroll
            for (int nt = 0; nt < 8; nt++) {
                const int col = nt * 8 + gi;
#pragma unroll
                for (int kc = 0; kc < 4; kc++) {
                    BhR[nt][kc][0] = Wh2[col * W_PAD + kc * 8 + tq];
                    BhR[nt][kc][1] = Wh2[col * W_PAD + kc * 8 + tq + 4];
                }
            }
        }

        const uint32_t* Abuf = sm + st * STAGE_U32;

        // ---- compute: 1 m-tile x 8 n-tiles, 4 k-chunks (k=16), 1 term ----
        float acc[8][4];
#pragma unroll
        for (int nt = 0; nt < 8; nt++)
#pragma unroll
            for (int r = 0; r < 4; r++) acc[nt][r] = 0.f;

#pragma unroll
        for (int kc = 0; kc < 4; kc++) {
            uint32_t ah[4];
            {
                const uint32_t* p = Abuf + (EB + gi) * A_STRIDE + kc * 8 + tq;
                ah[0] = p[0];
                ah[1] = p[8 * A_STRIDE];
                ah[2] = p[4];
                ah[3] = p[8 * A_STRIDE + 4];
            }
#pragma unroll
            for (int nt = 0; nt < 8; nt++) mma_f16(acc[nt], ah, BhR[nt][kc]);
        }

        // ---- scatter: per edge row, thread owns couts {16g+4tq..+3}, g=0..3 ----
        const int* oi = out_idx + (size_t)k * nE + ebase;
        {
            const int r0 = EB + gi;
            const int og0 = (ebase + r0 < nE) ? __ldg(oi + r0) : -1;
            const int og1 = (ebase + r0 + 8 < nE) ? __ldg(oi + r0 + 8) : -1;
#pragma unroll
            for (int g = 0; g < 4; g++) {
                const int cbase = 16 * g + 4 * tq;
                if (og0 >= 0)
                    red_add_v4(yout + (size_t)og0 * 64 + cbase,
                               acc[2 * g][0], acc[2 * g][1],
                               acc[2 * g + 1][0], acc[2 * g + 1][1]);
                if (og1 >= 0)
                    red_add_v4(yout + (size_t)og1 * 64 + cbase,
                               acc[2 * g][2], acc[2 * g][3],
                               acc[2 * g + 1][2], acc[2 * g + 1][3]);
            }
        }
        // no trailing barrier (next iteration's post-wait barrier covers WAR)
    }
}

// ---------------------------------------------------------------------------
// xc[row] = fp16 of (optionally BN+ReLU of) src row. Thread j: channels 2j,2j+1.
template <bool BN>
__global__ __launch_bounds__(256) void convert_kernel(const float2* __restrict__ src,
                                                      uint32_t* __restrict__ dst,
                                                      const float* __restrict__ bnp,
                                                      int n32) {
    int i = blockIdx.x * blockDim.x + threadIdx.x;
    if (i >= n32) return;
    int j = i & 31, row = i >> 5;
    float2 v = src[i];
    if (BN) {
        float2 sc = *(const float2*)(bnp + 2 * j);
        float2 sh = *(const float2*)(bnp + 64 + 2 * j);
        v.x = fmaxf(fmaf(v.x, sc.x, sh.x), 0.f);
        v.y = fmaxf(fmaf(v.y, sc.y, sh.y), 0.f);
    }
    __half2 hb = __floats2half2_rn(v.x, v.y);
    dst[(size_t)row * 32 + j] = *reinterpret_cast<uint32_t*>(&hb);
}

// ---------------------------------------------------------------------------
__global__ __launch_bounds__(256) void stats_kernel(const float* __restrict__ y,
                                                    float2* __restrict__ sums, int n) {
    const int lane = threadIdx.x & 31;
    const int warp = threadIdx.x >> 5;
    const int wpb = blockDim.x >> 5;

    float2 s = {0.f, 0.f}, q = {0.f, 0.f};
    for (int r = blockIdx.x * wpb + warp; r < n; r += gridDim.x * wpb) {
        float2 v = *(const float2*)(y + (size_t)r * 64 + 2 * lane);
        s.x += v.x; s.y += v.y;
        q.x = fmaf(v.x, v.x, q.x);
        q.y = fmaf(v.y, v.y, q.y);
    }
    __shared__ float2 sh_s[8][32], sh_q[8][32];
    sh_s[warp][lane] = s;
    sh_q[warp][lane] = q;
    __syncthreads();
    if (warp == 0) {
        for (int i = 1; i < wpb; i++) {
            s.x += sh_s[i][lane].x; s.y += sh_s[i][lane].y;
            q.x += sh_q[i][lane].x; q.y += sh_q[i][lane].y;
        }
        atomicAdd(&sums[lane], s);
        atomicAdd(&sums[32 + lane], q);
    }
}

__global__ void finalize_kernel(const float2* __restrict__ sums,
                                const float* __restrict__ gamma,
                                const float* __restrict__ beta,
                                float* __restrict__ bnout, float invN) {
    int l = threadIdx.x;  // 0..31 -> channels 2l, 2l+1
    float2 s = sums[l], q = sums[32 + l];
    float m0 = s.x * invN, m1 = s.y * invN;
    float v0 = fmaf(q.x, invN, -m0 * m0);
    float v1 = fmaf(q.y, invN, -m1 * m1);
    float sc0 = gamma[2 * l] * rsqrtf(v0 + 1e-5f);
    float sc1 = gamma[2 * l + 1] * rsqrtf(v1 + 1e-5f);
    bnout[2 * l] = sc0;
    bnout[2 * l + 1] = sc1;
    bnout[64 + 2 * l] = beta[2 * l] - m0 * sc0;
    bnout[64 + 2 * l + 1] = beta[2 * l + 1] - m1 * sc1;
}

__global__ __launch_bounds__(256) void final_kernel(const float4* __restrict__ y2,
                                                    const float4* __restrict__ x,
                                                    const float* __restrict__ bn,
                                                    float4* __restrict__ out, int n4) {
    int i = blockIdx.x * blockDim.x + threadIdx.x;
    if (i >= n4) return;
    int c4 = (i & 15) * 4;
    float4 v = y2[i], xr = x[i];
    float4 sc = *(const float4*)(bn + c4);
    float4 sh = *(const float4*)(bn + 64 + c4);
    float4 o;
    o.x = fmaxf(fmaf(v.x, sc.x, sh.x) + xr.x, 0.f);
    o.y = fmaxf(fmaf(v.y, sc.y, sh.y) + xr.y, 0.f);
    o.z = fmaxf(fmaf(v.z, sc.z, sh.z) + xr.z, 0.f);
    o.w = fmaxf(fmaf(v.w, sc.w, sh.w) + xr.w, 0.f);
    out[i] = o;
}

// ---------------------------------------------------------------------------
extern "C" void kernel_launch(void* const* d_in, const int* in_sizes, int n_in,
                              void* d_out, int out_size) {
    const float* x      = (const float*)d_in[0];
    const float* W1     = (const float*)d_in[2];
    const float* gamma1 = (const float*)d_in[3];
    const float* beta1  = (const float*)d_in[4];
    const float* W2     = (const float*)d_in[5];
    const float* gamma2 = (const float*)d_in[6];
    const float* beta2  = (const float*)d_in[7];
    const int* in_idx   = (const int*)d_in[8];
    const int* out_idx  = (const int*)d_in[9];

    const int N = in_sizes[0] / 64;
    const int K = in_sizes[2] / (64 * 64);

    float *y1, *y2, *bn;
    uint32_t *xc, *y1c;
    float2* stats;
    cudaGetSymbolAddress((void**)&xc, g_xc);
    cudaGetSymbolAddress((void**)&y1c, g_y1c);
    cudaGetSymbolAddress((void**)&y1, g_y1);
    cudaGetSymbolAddress((void**)&y2, g_y2);
    cudaGetSymbolAddress((void**)&stats, g_stats);
    cudaGetSymbolAddress((void**)&bn, g_bn);

    cudaFuncSetAttribute(conv_mma_kernel,
                         cudaFuncAttributeMaxDynamicSharedMemorySize, SMEM_BYTES);

    cudaMemsetAsync(y1, 0, (size_t)N * 64 * sizeof(float));
    cudaMemsetAsync(y2, 0, (size_t)N * 64 * sizeof(float));
    cudaMemsetAsync(stats, 0, 4 * 32 * sizeof(float2));

    const int NB = 296;  // 2 CTAs per SM
    const float invN = 1.0f / (float)N;
    const int n32 = N * 32;

    // layer 1
    convert_kernel<false><<<(n32 + 255) / 256, 256>>>((const float2*)x, xc, nullptr, n32);
    conv_mma_kernel<<<NB, 256, SMEM_BYTES>>>(xc, W1, in_idx, out_idx, y1, N, K, NB);
    stats_kernel<<<256, 256>>>(y1, stats, N);
    finalize_kernel<<<1, 32>>>(stats, gamma1, beta1, bn, invN);

    // layer 2 (BN1 + ReLU folded into the convert)
    convert_kernel<true><<<(n32 + 255) / 256, 256>>>((const float2*)y1, y1c, bn, n32);
    conv_mma_kernel<<<NB, 256, SMEM_BYTES>>>(y1c, W2, in_idx, out_idx, y2, N, K, NB);
    stats_kernel<<<256, 256>>>(y2, stats + 64, N);
    finalize_kernel<<<1, 32>>>(stats + 64, gamma2, beta2, bn + 128, invN);

    // epilogue: BN2 + residual + ReLU
    final_kernel<<<(N * 16 + 255) / 256, 256>>>((const float4*)y2, (const float4*)x,
                                                bn + 128, (float4*)d_out, N * 16);
}

// round 17
// speedup vs baseline: 2.2181x; 1.0350x over previous
#include <cuda_runtime.h>
#include <cuda_fp16.h>
#include <cstdint>

// ============================================================================
// ResidualBlockWithPointsBase — FP16 1-term mma.sync, 4 pipelines/SM
//   xc  = fp16(x);  y1 = conv(xc, W1); stats1
//   y1c = fp16(relu(bn1(y1)))  [bn computed inline from stats]
//   y2  = conv(y1c, W2); stats2;  out = relu(bn2(y2) + x) [bn inline]
// conv: 128-thread CTAs (4 warps, 64-edge tiles), 4 CTAs/SM, 4-stage all-TMA
//   gather (128B/row fp16), prefetch distance 3, one __syncthreads per tile.
//   Warp owns 16 edges x all 64 couts; W fp16 fragments register-resident.
//   Single-term mma.m16n8k16. red.global.add.v4.f32 scatter (col-permuted).
// ============================================================================

#define MAXN 100352

__device__ uint32_t g_xc[MAXN * 32];   // [row][fp16x2 pairs 0..31]
__device__ uint32_t g_y1c[MAXN * 32];
__device__ float g_y[2 * MAXN * 64];   // y1 | y2
__device__ float2 g_stats[4 * 32];
__device__ float g_bn[4 * 64];         // (unused placeholder, kept for layout)

__device__ __forceinline__ void mma_f16(float* d, const uint32_t* a, const uint32_t* b) {
    asm volatile(
        "mma.sync.aligned.m16n8k16.row.col.f32.f16.f16.f32 "
        "{%0,%1,%2,%3}, {%4,%5,%6,%7}, {%8,%9}, {%0,%1,%2,%3};"
        : "+f"(d[0]), "+f"(d[1]), "+f"(d[2]), "+f"(d[3])
        : "r"(a[0]), "r"(a[1]), "r"(a[2]), "r"(a[3]), "r"(b[0]), "r"(b[1]));
}
__device__ __forceinline__ void red_add_v4(float* g, float a, float b, float c, float d) {
    asm volatile("red.global.add.v4.f32 [%0], {%1, %2, %3, %4};"
                 :: "l"(g), "f"(a), "f"(b), "f"(c), "f"(d) : "memory");
}

#define MBAR_WAIT(a, ph) do {                                                     \
    asm volatile("{\n\t.reg .pred P1;\n\tWL_%=:\n\t"                              \
        "mbarrier.try_wait.parity.acquire.cta.shared::cta.b64 P1, [%0], %1, 0x989680;\n\t" \
        "@P1 bra.uni WD_%=;\n\tbra.uni WL_%=;\n\tWD_%=:\n\t}"                     \
        :: "r"(a), "r"(ph) : "memory");                                           \
} while (0)

// smem layout (u32 units) — 64-edge tiles
#define A_STRIDE 36                            // 144B/row (16B aligned), 128B payload
#define TROWS 64
#define STAGE_U32 (TROWS * A_STRIDE)           // 2304 u32 per stage
#define NSTAGE 4
#define OFF_WH (NSTAGE * STAGE_U32)            // 9216
#define W_PAD 36
#define OFF_MBAR (OFF_WH + 64 * W_PAD)         // 11520 (byte 46080, 8B aligned)
#define SMEM_U32 (OFF_MBAR + 2 * NSTAGE)
#define SMEM_BYTES (SMEM_U32 * 4)              // 46112

#define TILE_BYTES (TROWS * 128u)              // 8192
#define PFD 3                                  // prefetch distance

// ---------------------------------------------------------------------------
__global__ __launch_bounds__(128, 4) void conv_mma_kernel(
    const uint32_t* __restrict__ xc,  // [N][32] u32 fp16x2 pairs
    const float* __restrict__ W,      // [K][64][64]
    const int* __restrict__ in_idx, const int* __restrict__ out_idx,
    float* __restrict__ yout,         // [N][64] pre-zeroed
    int nE, int K, int nblk) {
    extern __shared__ uint32_t sm[];
    uint32_t* Wh2 = sm + OFF_WH;
    const uint32_t smb = (uint32_t)__cvta_generic_to_shared(sm);

    const int tid = threadIdx.x;
    const int lane = tid & 31;
    const int wid = tid >> 5;          // 0..3
    const int gi = lane >> 2;
    const int tq = lane & 3;
    const int EB = wid * 16;           // warp's edge base (16 edges, all 64 couts)

    const int tilesPerK = (nE + TROWS - 1) / TROWS;
    const int total = K * tilesPerK;
    const int chunk = (total + nblk - 1) / nblk;
    const int it0 = blockIdx.x * chunk;
    const int it1 = min(it0 + chunk, total);
    if (it0 >= it1) return;

    if (tid == 0) {
#pragma unroll
        for (int s = 0; s < NSTAGE; s++)
            asm volatile("mbarrier.init.shared.b64 [%0], 1;"
                         :: "r"(smb + 4 * OFF_MBAR + 8 * s) : "memory");
        asm volatile("fence.proxy.async.shared::cta;" ::: "memory");
    }
    __syncthreads();

    auto load_idx = [&](int item) -> int {
        int k = item / tilesPerK;
        int e = (item - k * tilesPerK) * TROWS + tid;
        return (e < nE) ? __ldg(in_idx + (size_t)k * nE + e) : 0;
    };
    auto issue = [&](int item, int src_row) {
        const uint32_t st = (uint32_t)((item - it0) % NSTAGE);
        const uint32_t mb = smb + 4 * OFF_MBAR + 8 * st;
        if (tid == 0)
            asm volatile("mbarrier.arrive.expect_tx.shared.b64 _, [%0], %1;"
                         :: "r"(mb), "r"(TILE_BYTES) : "memory");
        if (tid < TROWS) {
            const uint32_t* src = xc + (size_t)src_row * 32;
            uint32_t dst = smb + 4 * st * STAGE_U32 + (uint32_t)tid * (A_STRIDE * 4);
            asm volatile(
                "cp.async.bulk.shared::cluster.global.mbarrier::complete_tx::bytes "
                "[%0], [%1], %2, [%3];"
                :: "r"(dst), "l"(src), "r"(128u), "r"(mb) : "memory");
        }
    };

    int cur_k = -1;
    uint32_t BhR[8][4][2];  // W fp16 fragments, all 8 n-tiles, per k

    int nidx;
#pragma unroll
    for (int d = 0; d < PFD; d++) {
        if (it0 + d < it1) {
            nidx = (tid < TROWS) ? load_idx(it0 + d) : 0;
            issue(it0 + d, nidx);
        }
    }
    nidx = (tid < TROWS && it0 + PFD < it1) ? load_idx(it0 + PFD) : 0;

    for (int item = it0; item < it1; item++) {
        const int k = item / tilesPerK;
        const int tile = item - k * tilesPerK;
        const int ebase = tile * TROWS;
        const int rel = item - it0;
        const int st = rel % NSTAGE;

        MBAR_WAIT(smb + 4 * OFF_MBAR + 8 * st, (rel / NSTAGE) & 1);
        __syncthreads();

        if (item + PFD < it1) {
            issue(item + PFD, nidx);
            nidx = (tid < TROWS && item + PFD + 1 < it1) ? load_idx(item + PFD + 1) : 0;
        }

        if (k != cur_k) {  // W restage (smem bounce) + load fragments into regs
            cur_k = k;
            const float* Wk = W + (size_t)k * 4096;
            for (int i = tid; i < 2048; i += 128) {
                int colP = i >> 5, j = i & 31;  // j = k-pair (k = 2j, 2j+1)
                int l16 = colP & 15;
                // inverse column permutation (for v4 scatter)
                int Lcol = (colP & ~15) + 4 * ((l16 >> 1) & 3) + 2 * ((l16 >> 3) & 1) + (l16 & 1);
                float w0 = __ldg(Wk + (size_t)(2 * j) * 64 + Lcol);
                float w1 = __ldg(Wk + (size_t)(2 * j + 1) * 64 + Lcol);
                __half2 w2 = __floats2half2_rn(w0, w1);
                Wh2[colP * W_PAD + j] = *reinterpret_cast<uint32_t*>(&w2);
            }
            __syncthreads();
#pragma unroll
            for (int nt = 0; nt < 8; nt++) {
                const int col = nt * 8 + gi;
#pragma unroll
                for (int kc = 0; kc < 4; kc++) {
                    BhR[nt][kc][0] = Wh2[col * W_PAD + kc * 8 + tq];
                    BhR[nt][kc][1] = Wh2[col * W_PAD + kc * 8 + tq + 4];
                }
            }
        }

        const uint32_t* Abuf = sm + st * STAGE_U32;

        // ---- compute: 1 m-tile x 8 n-tiles, 4 k-chunks (k=16), 1 term ----
        float acc[8][4];
#pragma unroll
        for (int nt = 0; nt < 8; nt++)
#pragma unroll
            for (int r = 0; r < 4; r++) acc[nt][r] = 0.f;

#pragma unroll
        for (int kc = 0; kc < 4; kc++) {
            uint32_t ah[4];
            {
                const uint32_t* p = Abuf + (EB + gi) * A_STRIDE + kc * 8 + tq;
                ah[0] = p[0];
                ah[1] = p[8 * A_STRIDE];
                ah[2] = p[4];
                ah[3] = p[8 * A_STRIDE + 4];
            }
#pragma unroll
            for (int nt = 0; nt < 8; nt++) mma_f16(acc[nt], ah, BhR[nt][kc]);
        }

        // ---- scatter: per edge row, thread owns couts {16g+4tq..+3}, g=0..3 ----
        const int* oi = out_idx + (size_t)k * nE + ebase;
        {
            const int r0 = EB + gi;
            const int og0 = (ebase + r0 < nE) ? __ldg(oi + r0) : -1;
            const int og1 = (ebase + r0 + 8 < nE) ? __ldg(oi + r0 + 8) : -1;
#pragma unroll
            for (int g = 0; g < 4; g++) {
                const int cbase = 16 * g + 4 * tq;
                if (og0 >= 0)
                    red_add_v4(yout + (size_t)og0 * 64 + cbase,
                               acc[2 * g][0], acc[2 * g][1],
                               acc[2 * g + 1][0], acc[2 * g + 1][1]);
                if (og1 >= 0)
                    red_add_v4(yout + (size_t)og1 * 64 + cbase,
                               acc[2 * g][2], acc[2 * g][3],
                               acc[2 * g + 1][2], acc[2 * g + 1][3]);
            }
        }
        // no trailing barrier (next iteration's post-wait barrier covers WAR)
    }
}

// ---------------------------------------------------------------------------
// BN scale/shift for channel pair (2j, 2j+1) computed inline from raw stats.
__device__ __forceinline__ void bn_pair(const float2* sums, const float* gamma,
                                        const float* beta, int j, float invN,
                                        float2& sc, float2& sh) {
    float2 s = sums[j], q = sums[32 + j];
    float m0 = s.x * invN, m1 = s.y * invN;
    float v0 = fmaf(q.x, invN, -m0 * m0);
    float v1 = fmaf(q.y, invN, -m1 * m1);
    sc.x = gamma[2 * j] * rsqrtf(v0 + 1e-5f);
    sc.y = gamma[2 * j + 1] * rsqrtf(v1 + 1e-5f);
    sh.x = beta[2 * j] - m0 * sc.x;
    sh.y = beta[2 * j + 1] - m1 * sc.y;
}

// xc[row] = fp16 of (optionally BN+ReLU of) src row. Thread j: channels 2j,2j+1.
template <bool BN>
__global__ __launch_bounds__(256) void convert_kernel(const float2* __restrict__ src,
                                                      uint32_t* __restrict__ dst,
                                                      const float2* __restrict__ sums,
                                                      const float* __restrict__ gamma,
                                                      const float* __restrict__ beta,
                                                      float invN, int n32) {
    int i = blockIdx.x * blockDim.x + threadIdx.x;
    if (i >= n32) return;
    int j = i & 31, row = i >> 5;
    float2 v = src[i];
    if (BN) {
        float2 sc, sh;
        bn_pair(sums, gamma, beta, j, invN, sc, sh);
        v.x = fmaxf(fmaf(v.x, sc.x, sh.x), 0.f);
        v.y = fmaxf(fmaf(v.y, sc.y, sh.y), 0.f);
    }
    __half2 hb = __floats2half2_rn(v.x, v.y);
    dst[(size_t)row * 32 + j] = *reinterpret_cast<uint32_t*>(&hb);
}

// ---------------------------------------------------------------------------
__global__ __launch_bounds__(256) void stats_kernel(const float* __restrict__ y,
                                                    float2* __restrict__ sums, int n) {
    const int lane = threadIdx.x & 31;
    const int warp = threadIdx.x >> 5;
    const int wpb = blockDim.x >> 5;

    float2 s = {0.f, 0.f}, q = {0.f, 0.f};
    for (int r = blockIdx.x * wpb + warp; r < n; r += gridDim.x * wpb) {
        float2 v = *(const float2*)(y + (size_t)r * 64 + 2 * lane);
        s.x += v.x; s.y += v.y;
        q.x = fmaf(v.x, v.x, q.x);
        q.y = fmaf(v.y, v.y, q.y);
    }
    __shared__ float2 sh_s[8][32], sh_q[8][32];
    sh_s[warp][lane] = s;
    sh_q[warp][lane] = q;
    __syncthreads();
    if (warp == 0) {
        for (int i = 1; i < wpb; i++) {
            s.x += sh_s[i][lane].x; s.y += sh_s[i][lane].y;
            q.x += sh_q[i][lane].x; q.y += sh_q[i][lane].y;
        }
        atomicAdd(&sums[lane], s);
        atomicAdd(&sums[32 + lane], q);
    }
}

// out = relu(bn2(y2) + x), bn2 computed inline from raw stats
__global__ __launch_bounds__(256) void final_kernel(const float2* __restrict__ y2,
                                                    const float2* __restrict__ x,
                                                    const float2* __restrict__ sums,
                                                    const float* __restrict__ gamma,
                                                    const float* __restrict__ beta,
                                                    float invN,
                                                    float2* __restrict__ out, int n32) {
    int i = blockIdx.x * blockDim.x + threadIdx.x;
    if (i >= n32) return;
    int j = i & 31;
    float2 sc, sh;
    bn_pair(sums, gamma, beta, j, invN, sc, sh);
    float2 v = y2[i], xr = x[i];
    float2 o;
    o.x = fmaxf(fmaf(v.x, sc.x, sh.x) + xr.x, 0.f);
    o.y = fmaxf(fmaf(v.y, sc.y, sh.y) + xr.y, 0.f);
    out[i] = o;
}

// ---------------------------------------------------------------------------
extern "C" void kernel_launch(void* const* d_in, const int* in_sizes, int n_in,
                              void* d_out, int out_size) {
    const float* x      = (const float*)d_in[0];
    const float* W1     = (const float*)d_in[2];
    const float* gamma1 = (const float*)d_in[3];
    const float* beta1  = (const float*)d_in[4];
    const float* W2     = (const float*)d_in[5];
    const float* gamma2 = (const float*)d_in[6];
    const float* beta2  = (const float*)d_in[7];
    const int* in_idx   = (const int*)d_in[8];
    const int* out_idx  = (const int*)d_in[9];

    const int N = in_sizes[0] / 64;
    const int K = in_sizes[2] / (64 * 64);

    float* ybuf;
    uint32_t *xc, *y1c;
    float2* stats;
    cudaGetSymbolAddress((void**)&xc, g_xc);
    cudaGetSymbolAddress((void**)&y1c, g_y1c);
    cudaGetSymbolAddress((void**)&ybuf, g_y);
    cudaGetSymbolAddress((void**)&stats, g_stats);
    float* y1 = ybuf;
    float* y2 = ybuf + (size_t)MAXN * 64;

    cudaFuncSetAttribute(conv_mma_kernel,
                         cudaFuncAttributeMaxDynamicSharedMemorySize, SMEM_BYTES);

    cudaMemsetAsync(ybuf, 0, 2 * (size_t)MAXN * 64 * sizeof(float));
    cudaMemsetAsync(stats, 0, 4 * 32 * sizeof(float2));

    const int NB = 592;  // 4 CTAs per SM x 148
    const float invN = 1.0f / (float)N;
    const int n32 = N * 32;

    // layer 1
    convert_kernel<false><<<(n32 + 255) / 256, 256>>>((const float2*)x, xc, nullptr,
                                                      nullptr, nullptr, invN, n32);
    conv_mma_kernel<<<NB, 128, SMEM_BYTES>>>(xc, W1, in_idx, out_idx, y1, N, K, NB);
    stats_kernel<<<256, 256>>>(y1, stats, N);

    // layer 2 (BN1 + ReLU + finalize folded into the convert)
    convert_kernel<true><<<(n32 + 255) / 256, 256>>>((const float2*)y1, y1c, stats,
                                                     gamma1, beta1, invN, n32);
    conv_mma_kernel<<<NB, 128, SMEM_BYTES>>>(y1c, W2, in_idx, out_idx, y2, N, K, NB);
    stats_kernel<<<256, 256>>>(y2, stats + 64, N);

    // epilogue: BN2 (inline finalize) + residual + ReLU
    final_kernel<<<(n32 + 255) / 256, 256>>>((const float2*)y2, (const float2*)x,
                                             stats + 64, gamma2, beta2, invN,
                                             (float2*)d_out, n32);
}